// round 13
// baseline (speedup 1.0000x reference)
#include <cuda_runtime.h>
#include <cuda_fp16.h>
#include <mma.h>
#include <cstdint>

using namespace nvcuda;

// Shapes: B=4, P=2048 -> T=8192 tokens, D=1024, H=16, KV=8, HD=64, F=4096, E=16, FE=256
#define T_TOK 8192
#define NPOS  2048

// ---------------- scratch (device globals) ----------------
__device__ __half sc_hh  [8192*1024];          // rmsnorm out (fp16)
__device__ __half sc_qkv [8192*2048];          // q|k|v packed fp16
__device__ __half sc_aoh [8192*1024];          // attention out fp16
__device__ __half sc_act [(size_t)8192*8192];  // swiglu activations fp16
__device__ float  sc_cos [2048*32];
__device__ float  sc_sin [2048*32];
__device__ float  sc_bias[2048];
__device__ __half sc_w   [28311552];           // packed fp16 weights

// packed weight offsets (elements)
#define OFF_QKV 0                 // [1024, 2048]
#define OFF_WO  2097152           // [1024, 1024]
#define OFF_GU  3145728           // [1024, 16384] col-interleaved g/u
#define OFF_DN  19922944          // [8192, 1024]

// ---------------- weight packing ----------------
__global__ __launch_bounds__(256)
void f2h_kernel(const float* __restrict__ s, __half* __restrict__ d)
{
    size_t i = ((size_t)blockIdx.x * 256 + threadIdx.x) * 8;
    float4 a = *(const float4*)(s + i);
    float4 b = *(const float4*)(s + i + 4);
    __half2 h0 = __floats2half2_rn(a.x, a.y);
    __half2 h1 = __floats2half2_rn(a.z, a.w);
    __half2 h2 = __floats2half2_rn(b.x, b.y);
    __half2 h3 = __floats2half2_rn(b.z, b.w);
    uint4 o;
    o.x = *(uint32_t*)&h0; o.y = *(uint32_t*)&h1;
    o.z = *(uint32_t*)&h2; o.w = *(uint32_t*)&h3;
    *(uint4*)(d + i) = o;
}

__global__ __launch_bounds__(256)
void pack_qkv(const float* __restrict__ wq, const float* __restrict__ wk,
              const float* __restrict__ wv, __half* __restrict__ d)
{
    int i = blockIdx.x * 256 + threadIdx.x;     // 1024*2048
    int r = i >> 11, c = i & 2047;
    float v;
    if (c < 1024)      v = wq[r * 1024 + c];
    else if (c < 1536) v = wk[r * 512 + (c - 1024)];
    else               v = wv[r * 512 + (c - 1536)];
    d[i] = __float2half(v);
}

__global__ __launch_bounds__(256)
void pack_bias(const float* __restrict__ bq, const float* __restrict__ bk,
               const float* __restrict__ bv, float* __restrict__ d)
{
    int c = blockIdx.x * 256 + threadIdx.x;     // 2048
    float v;
    if (c < 1024)      v = bq[c];
    else if (c < 1536) v = bk[c - 1024];
    else               v = bv[c - 1536];
    d[c] = v;
}

// interleaved: col 2j = gate_j, col 2j+1 = up_j ; j<4096 dense, else expert
__global__ __launch_bounds__(256)
void pack_gu(const float* __restrict__ wg, const float* __restrict__ wu,
             const float* __restrict__ eg, const float* __restrict__ eu,
             __half* __restrict__ d)
{
    size_t i = (size_t)blockIdx.x * 256 + threadIdx.x;  // 1024*16384
    int r = (int)(i >> 14), c = (int)(i & 16383);
    int j = c >> 1, up = c & 1;
    float v;
    if (j < 4096)
        v = up ? wu[(size_t)r * 4096 + j] : wg[(size_t)r * 4096 + j];
    else {
        int jj = j - 4096, e = jj >> 8, f = jj & 255;
        size_t idx = ((size_t)e * 1024 + r) * 256 + f;
        v = up ? eu[idx] : eg[idx];
    }
    d[i] = __float2half(v);
}

__global__ __launch_bounds__(256)
void pack_down(const float* __restrict__ wd, const float* __restrict__ ed,
               __half* __restrict__ d)
{
    size_t i = (size_t)blockIdx.x * 256 + threadIdx.x;  // 8192*1024
    int r = (int)(i >> 10), c = (int)(i & 1023);
    float v;
    if (r < 4096) v = wd[(size_t)r * 1024 + c];
    else {
        int r2 = r - 4096, e = r2 >> 8, f = r2 & 255;
        v = ed[((size_t)e * 256 + f) * 1024 + c];
    }
    d[i] = __float2half(v);
}

// ---------------- rmsnorm (fp32 in -> fp16 out) ----------------
__global__ __launch_bounds__(256)
void rmsnorm_kernel(const float* __restrict__ x, const float* __restrict__ w,
                    __half* __restrict__ out)
{
    int t = blockIdx.x;
    const float* xr = x + (size_t)t * 1024;
    __half* orow = out + (size_t)t * 1024;
    int tid = threadIdx.x;

    float4 v = *(const float4*)(xr + tid * 4);
    float s = v.x*v.x + v.y*v.y + v.z*v.z + v.w*v.w;
    #pragma unroll
    for (int o = 16; o; o >>= 1) s += __shfl_xor_sync(0xffffffffu, s, o);
    __shared__ float ws[8];
    if ((tid & 31) == 0) ws[tid >> 5] = s;
    __syncthreads();
    if (tid < 8) {
        float t2 = ws[tid];
        #pragma unroll
        for (int o = 4; o; o >>= 1) t2 += __shfl_xor_sync(0xffu, t2, o);
        if (tid == 0) ws[0] = t2;
    }
    __syncthreads();
    float rinv = rsqrtf(ws[0] * (1.0f / 1024.0f) + 1e-6f);
    float4 wv = *(const float4*)(w + tid * 4);
    __half2 r0 = __floats2half2_rn(v.x * rinv * wv.x, v.y * rinv * wv.y);
    __half2 r1 = __floats2half2_rn(v.z * rinv * wv.z, v.w * rinv * wv.w);
    uint2 o;
    o.x = *(uint32_t*)&r0; o.y = *(uint32_t*)&r1;
    *(uint2*)(orow + tid * 4) = o;
}

// ---------------- pipelined fp16 GEMM, 4 warps x 64x64, KC=32, 4 stages -----
// 128 threads/CTA -> 2 CTAs/SM with up to 255 regs/thread (pipelining headroom)
// mode 0: C/Ch = A@B (+bias/res/accum)
// mode 1 (swiglu): B col-interleaved (g,u); writes act[M, N/2] = silu(g)*u*mask
#define GBK   32
#define GLDA  40
#define GLDB  136
#define ASTG  (128 * GLDA)
#define BSTG  (GBK * GLDB)
#define NSTG  4
#define GSMEM ((NSTG * (ASTG + BSTG)) * 2)   // 75776 B -> 2 CTAs/SM

__device__ __forceinline__ void cp16(uint32_t saddr, const void* g)
{
    asm volatile("cp.async.cg.shared.global [%0], [%1], 16;\n" :: "r"(saddr), "l"(g));
}
#define CP_COMMIT() asm volatile("cp.async.commit_group;\n" ::)
#define CP_WAIT2()  asm volatile("cp.async.wait_group 2;\n" ::)
#define CP_WAIT0()  asm volatile("cp.async.wait_group 0;\n" ::)

__global__ __launch_bounds__(128)
void gemm_h(const __half* __restrict__ A, const __half* __restrict__ B,
            float* __restrict__ C, __half* __restrict__ Ch,
            int M, int N, int K,
            const float* __restrict__ bias, const float* __restrict__ res,
            int accum, int swiglu, const float* __restrict__ mask)
{
    extern __shared__ __half sm[];
    __half* As = sm;
    __half* Bs = sm + NSTG * ASTG;
    uint32_t smemBase = (uint32_t)__cvta_generic_to_shared(sm);

    int bm = blockIdx.y * 128, bn = blockIdx.x * 128;
    int tid = threadIdx.x, wid = tid >> 5, lane = tid & 31;
    int wm = (wid >> 1) * 64, wn = (wid & 1) * 64;

    wmma::fragment<wmma::accumulator, 16, 16, 16, float> acc[4][4];
    #pragma unroll
    for (int i = 0; i < 4; i++)
        #pragma unroll
        for (int j = 0; j < 4; j++) wmma::fill_fragment(acc[i][j], 0.0f);

    int nk = K / GBK;

    auto prefetch = [&](int s, int k0) {
        uint32_t as = smemBase + (uint32_t)(s * ASTG) * 2;
        uint32_t bs = smemBase + (uint32_t)(NSTG * ASTG + s * BSTG) * 2;
        // A: 128 rows x 4 chunks of 8 halves = 512 chunks, 4/thread
        #pragma unroll
        for (int it = 0; it < 4; it++) {
            int j = tid + it * 128;
            int r = j >> 2, c8 = j & 3;
            cp16(as + (uint32_t)(r * GLDA + c8 * 8) * 2,
                 A + (size_t)(bm + r) * K + k0 + c8 * 8);
        }
        // B: 32 rows x 16 chunks of 8 halves = 512 chunks, 4/thread
        #pragma unroll
        for (int it = 0; it < 4; it++) {
            int j = tid + it * 128;
            int r = j >> 4, c8 = j & 15;
            cp16(bs + (uint32_t)(r * GLDB + c8 * 8) * 2,
                 B + (size_t)(k0 + r) * N + bn + c8 * 8);
        }
    };

    prefetch(0, 0);        CP_COMMIT();
    prefetch(1, GBK);      CP_COMMIT();
    prefetch(2, 2 * GBK);  CP_COMMIT();

    for (int i = 0; i < nk; i++) {
        CP_WAIT2();
        __syncthreads();

        int s = i % NSTG;
        const __half* as = As + s * ASTG;
        const __half* bs = Bs + s * BSTG;
        #pragma unroll 1
        for (int kk = 0; kk < GBK; kk += 16) {
            wmma::fragment<wmma::matrix_a, 16, 16, 16, __half, wmma::row_major> af[4];
            #pragma unroll
            for (int ii = 0; ii < 4; ii++)
                wmma::load_matrix_sync(af[ii], as + (wm + ii * 16) * GLDA + kk, GLDA);
            #pragma unroll
            for (int jj = 0; jj < 4; jj++) {
                wmma::fragment<wmma::matrix_b, 16, 16, 16, __half, wmma::row_major> bf;
                wmma::load_matrix_sync(bf, bs + kk * GLDB + wn + jj * 16, GLDB);
                #pragma unroll
                for (int ii = 0; ii < 4; ii++)
                    wmma::mma_sync(acc[ii][jj], af[ii], bf, acc[ii][jj]);
            }
        }

        int next = i + NSTG - 1;
        if (next < nk) prefetch(next % NSTG, next * GBK);
        CP_COMMIT();
    }

    __syncthreads();

    float* buf = (float*)sm + wid * 256;
    int er = lane >> 1, ec0 = (lane & 1) * 8;   // swiglu mapping: row er, cols ec0..ec0+7
    #pragma unroll 1
    for (int i = 0; i < 4; i++)
        #pragma unroll 1
        for (int j = 0; j < 4; j++) {
            wmma::store_matrix_sync(buf, acc[i][j], 16, wmma::mem_row_major);
            __syncwarp();
            int r0 = bm + wm + i * 16, c0 = bn + wn + j * 16;
            if (swiglu) {
                // cols (even,odd) are (gate,up) pairs; act col = global_col/2
                int tok = r0 + er;
                int jb = (c0 >> 1) + (ec0 >> 1);      // 4 consecutive act cols
                float av[4];
                #pragma unroll
                for (int p = 0; p < 4; p++) {
                    float g = buf[er * 16 + ec0 + 2 * p];
                    float u = buf[er * 16 + ec0 + 2 * p + 1];
                    float a = g / (1.0f + __expf(-g)) * u;
                    int jc = jb + p;
                    if (jc >= 4096) a *= mask[(size_t)tok * 16 + ((jc - 4096) >> 8)];
                    av[p] = a;
                }
                __half2 h01 = __floats2half2_rn(av[0], av[1]);
                __half2 h23 = __floats2half2_rn(av[2], av[3]);
                uint2 o; o.x = *(uint32_t*)&h01; o.y = *(uint32_t*)&h23;
                *(uint2*)(Ch + (size_t)tok * (N >> 1) + jb) = o;
            } else {
                #pragma unroll
                for (int t2 = 0; t2 < 8; t2++) {
                    int e = lane * 8 + t2;
                    int rr = e >> 4, cc = e & 15;
                    float vv = buf[e];
                    if (bias) vv += bias[c0 + cc];
                    size_t ci = (size_t)(r0 + rr) * N + (c0 + cc);
                    if (res)   vv += res[ci];
                    if (accum) vv += C[ci];
                    if (Ch) Ch[ci] = __float2half(vv);
                    else    C[ci]  = vv;
                }
            }
            __syncwarp();
        }
}

// ---------------- RoPE ----------------
__global__ void rope_table(float* __restrict__ ct, float* __restrict__ st)
{
    int i = blockIdx.x * 256 + threadIdx.x;
    int p = i >> 5, j = i & 31;
    float inv = powf(10000.0f, -(float)j * (1.0f / 32.0f));
    float ang = (float)p * inv;
    float s, c;
    sincosf(ang, &s, &c);
    ct[i] = c; st[i] = s;
}

// q (16 heads, col 0) and k (8 heads, col 1024) in one launch
__global__ void rope_apply(__half* __restrict__ qkv,
                           const float* __restrict__ ct, const float* __restrict__ st)
{
    int i = blockIdx.x * 256 + threadIdx.x;      // T*24*32 total
    int j = i & 31;
    int hh = (i >> 5) % 24;
    int t = i / (24 * 32);
    int p = t & (NPOS - 1);
    int coff = (hh < 16) ? (hh * 64) : (1024 + (hh - 16) * 64);
    float c = ct[p * 32 + j], s = st[p * 32 + j];
    size_t base = (size_t)t * 2048 + coff;
    float v1 = __half2float(qkv[base + j]);
    float v2 = __half2float(qkv[base + 32 + j]);
    qkv[base + j]      = __float2half(v1 * c - v2 * s);
    qkv[base + 32 + j] = __float2half(v2 * c + v1 * s);
}

// ---------------- fp16 flash attention (causal, GQA 2:1, HD=64, 64-row) ------
#define FLD 72
#define FT  4608
#define FLASH_SMEM ((6 * FT) * 2 + (2 * FT + 192) * 4)
__global__ __launch_bounds__(256)
void flash16(const __half* __restrict__ qkv, __half* __restrict__ o)
{
    extern __shared__ __half smh[];
    __half* Qs = smh;
    __half* Ks = Qs + FT;
    __half* Vs = Ks + 2 * FT;
    __half* Ps = Vs + 2 * FT;
    float*  Ss = (float*)(Ps + FT);
    float*  Os = Ss + FT;
    float*  mrow = Os + FT;
    float*  lrow = mrow + 64;
    float*  crow = lrow + 64;
    uint32_t smemBase = (uint32_t)__cvta_generic_to_shared(smh);

    int qt = blockIdx.x, h = blockIdx.y, b = blockIdx.z;
    int tid = threadIdx.x, wid = tid >> 5;
    int kvh = h >> 1;

    const __half* qb = qkv + ((size_t)(b * NPOS + qt * 64)) * 2048 + h * 64;
    const __half2 sc8 = __floats2half2_rn(0.125f, 0.125f);
    for (int it = 0; it < 2; it++) {
        int j = tid + it * 256;
        int r = j >> 3, c8 = j & 7;
        uint4 raw = *(const uint4*)(qb + (size_t)r * 2048 + c8 * 8);
        __half2* hp = (__half2*)&raw;
        #pragma unroll
        for (int q2 = 0; q2 < 4; q2++) hp[q2] = __hmul2(hp[q2], sc8);
        *(uint4*)(Qs + r * FLD + c8 * 8) = raw;
    }
    for (int i = tid; i < 4096; i += 256) {
        int r = i >> 6, c = i & 63;
        Os[r * FLD + c] = 0.0f;
    }
    if (tid < 64) { mrow[tid] = -1e30f; lrow[tid] = 0.0f; }

    auto pf = [&](int kt, int bi) {
        const __half* kb = qkv + ((size_t)(b * NPOS + kt * 64)) * 2048 + 1024 + kvh * 64;
        uint32_t ks = smemBase + (uint32_t)(FT + bi * FT) * 2;
        uint32_t vs = smemBase + (uint32_t)(3 * FT + bi * FT) * 2;
        #pragma unroll
        for (int it = 0; it < 2; it++) {
            int j = tid + it * 256;
            int r = j >> 3, c8 = j & 7;
            cp16(ks + (uint32_t)(r * FLD + c8 * 8) * 2, kb + (size_t)r * 2048 + c8 * 8);
            cp16(vs + (uint32_t)(r * FLD + c8 * 8) * 2, kb + (size_t)r * 2048 + 512 + c8 * 8);
        }
    };

    pf(0, 0);
    CP_COMMIT();
    __syncthreads();

    int wm = (wid >> 1) * 16, wn = (wid & 1) * 32;

    for (int kt = 0; kt <= qt; kt++) {
        int bi = kt & 1;
        CP_WAIT0();
        __syncthreads();
        if (kt < qt) pf(kt + 1, bi ^ 1);
        CP_COMMIT();

        const __half* kcur = Ks + bi * FT;
        const __half* vcur = Vs + bi * FT;

        {
            wmma::fragment<wmma::accumulator, 16, 16, 16, float> sa[2];
            wmma::fill_fragment(sa[0], 0.0f);
            wmma::fill_fragment(sa[1], 0.0f);
            #pragma unroll
            for (int d = 0; d < 64; d += 16) {
                wmma::fragment<wmma::matrix_a, 16, 16, 16, __half, wmma::row_major> af;
                wmma::load_matrix_sync(af, Qs + wm * FLD + d, FLD);
                #pragma unroll
                for (int jj = 0; jj < 2; jj++) {
                    wmma::fragment<wmma::matrix_b, 16, 16, 16, __half, wmma::col_major> bf;
                    wmma::load_matrix_sync(bf, kcur + (wn + jj * 16) * FLD + d, FLD);
                    wmma::mma_sync(sa[jj], af, bf, sa[jj]);
                }
            }
            wmma::store_matrix_sync(Ss + wm * FLD + wn,      sa[0], FLD, wmma::mem_row_major);
            wmma::store_matrix_sync(Ss + wm * FLD + wn + 16, sa[1], FLD, wmma::mem_row_major);
        }
        __syncthreads();

        {
            int r = tid >> 2, pp = tid & 3;
            int qg = qt * 64 + r;
            float vals[16]; float mx = -1e30f;
            #pragma unroll
            for (int c = 0; c < 16; c++) {
                int col = pp * 16 + c;
                float sv = Ss[r * FLD + col];
                if (kt * 64 + col > qg) sv = -1e30f;
                vals[c] = sv; mx = fmaxf(mx, sv);
            }
            mx = fmaxf(mx, __shfl_xor_sync(0xffffffffu, mx, 1));
            mx = fmaxf(mx, __shfl_xor_sync(0xffffffffu, mx, 2));
            float mold = mrow[r];
            float mnew = fmaxf(mold, mx);
            float sum = 0.0f;
            #pragma unroll
            for (int c = 0; c < 16; c++) {
                float e = __expf(vals[c] - mnew);
                Ps[r * FLD + pp * 16 + c] = __float2half(e);
                sum += e;
            }
            sum += __shfl_xor_sync(0xffffffffu, sum, 1);
            sum += __shfl_xor_sync(0xffffffffu, sum, 2);
            if (pp == 0) {
                float cc = __expf(mold - mnew);
                lrow[r] = lrow[r] * cc + sum;
                mrow[r] = mnew;
                crow[r] = cc;
            }
        }
        __syncthreads();

        {
            wmma::fragment<wmma::accumulator, 16, 16, 16, float> pv[2];
            wmma::fill_fragment(pv[0], 0.0f);
            wmma::fill_fragment(pv[1], 0.0f);
            #pragma unroll
            for (int kk = 0; kk < 64; kk += 16) {
                wmma::fragment<wmma::matrix_a, 16, 16, 16, __half, wmma::row_major> af;
                wmma::load_matrix_sync(af, Ps + wm * FLD + kk, FLD);
                #pragma unroll
                for (int jj = 0; jj < 2; jj++) {
                    wmma::fragment<wmma::matrix_b, 16, 16, 16, __half, wmma::row_major> bf;
                    wmma::load_matrix_sync(bf, vcur + kk * FLD + wn + jj * 16, FLD);
                    wmma::mma_sync(pv[jj], af, bf, pv[jj]);
                }
            }
            wmma::store_matrix_sync(Ss + wm * FLD + wn,      pv[0], FLD, wmma::mem_row_major);
            wmma::store_matrix_sync(Ss + wm * FLD + wn + 16, pv[1], FLD, wmma::mem_row_major);
        }
        __syncthreads();

        for (int i = tid; i < 4096; i += 256) {
            int r = i >> 6, c = i & 63;
            Os[r * FLD + c] = Os[r * FLD + c] * crow[r] + Ss[r * FLD + c];
        }
        __syncthreads();
    }

    __half* ob = o + ((size_t)(b * NPOS + qt * 64)) * 1024 + h * 64;
    for (int i = tid; i < 4096; i += 256) {
        int r = i >> 6, c = i & 63;
        ob[(size_t)r * 1024 + c] = __float2half(Os[r * FLD + c] / lrow[r]);
    }
}

// ---------------- launch ----------------
extern "C" void kernel_launch(void* const* d_in, const int* in_sizes, int n_in,
                              void* d_out, int out_size)
{
    const float* x       = (const float*)d_in[0];
    const float* emask   = (const float*)d_in[1];
    const float* ln1     = (const float*)d_in[2];
    const float* wq      = (const float*)d_in[3];
    const float* bq      = (const float*)d_in[4];
    const float* wk      = (const float*)d_in[5];
    const float* bk      = (const float*)d_in[6];
    const float* wv      = (const float*)d_in[7];
    const float* bv      = (const float*)d_in[8];
    const float* wo      = (const float*)d_in[9];
    const float* ln2     = (const float*)d_in[10];
    const float* w_gate  = (const float*)d_in[11];
    const float* w_up    = (const float*)d_in[12];
    const float* w_down  = (const float*)d_in[13];
    const float* we_gate = (const float*)d_in[14];
    const float* we_up   = (const float*)d_in[15];
    const float* we_down = (const float*)d_in[16];
    float* out = (float*)d_out;

    __half *hh, *qkv, *aoh, *act, *w;
    float *ct, *st, *bias;
    cudaGetSymbolAddress((void**)&hh,   sc_hh);
    cudaGetSymbolAddress((void**)&qkv,  sc_qkv);
    cudaGetSymbolAddress((void**)&aoh,  sc_aoh);
    cudaGetSymbolAddress((void**)&act,  sc_act);
    cudaGetSymbolAddress((void**)&w,    sc_w);
    cudaGetSymbolAddress((void**)&ct,   sc_cos);
    cudaGetSymbolAddress((void**)&st,   sc_sin);
    cudaGetSymbolAddress((void**)&bias, sc_bias);

    cudaFuncSetAttribute(flash16, cudaFuncAttributeMaxDynamicSharedMemorySize, FLASH_SMEM);
    cudaFuncSetAttribute(gemm_h, cudaFuncAttributeMaxDynamicSharedMemorySize, GSMEM);

    const int M = T_TOK;
    dim3 thr(128);

    // early ordering so the ncu capture index lands on a GEMM launch
    pack_bias<<<8, 256>>>(bq, bk, bv, bias);
    pack_qkv<<<8192, 256>>>(wq, wk, wv, w + OFF_QKV);
    rmsnorm_kernel<<<M, 256>>>(x, ln1, hh);

    // launch #4: QKV projection (bias folded)
    gemm_h<<<dim3(16, 64), thr, GSMEM>>>(hh, w + OFF_QKV, nullptr, qkv,
                                         M, 2048, 1024, bias, nullptr, 0, 0, nullptr);

    pack_gu<<<65536, 256>>>(w_gate, w_up, we_gate, we_up, w + OFF_GU);
    f2h_kernel<<<512, 256>>>(wo, w + OFF_WO);
    pack_down<<<32768, 256>>>(w_down, we_down, w + OFF_DN);
    rope_table<<<256, 256>>>(ct, st);
    rope_apply<<<24576, 256>>>(qkv, ct, st);

    flash16<<<dim3(32, 16, 4), 256, FLASH_SMEM>>>(qkv, aoh);

    // out = x + attn @ Wo
    gemm_h<<<dim3(8, 64), thr, GSMEM>>>(aoh, w + OFF_WO, out, nullptr,
                                        M, 1024, 1024, nullptr, x, 0, 0, nullptr);

    rmsnorm_kernel<<<M, 256>>>(out, ln2, hh);

    // fused gate|up (+experts) GEMM with swiglu epilogue -> act[T, 8192]
    gemm_h<<<dim3(128, 64), thr, GSMEM>>>(hh, w + OFF_GU, nullptr, act,
                                          M, 16384, 1024, nullptr, nullptr, 0, 1, emask);

    // fused down: out += act @ [Wd ; Ed]
    gemm_h<<<dim3(8, 64), thr, GSMEM>>>(act, w + OFF_DN, out, nullptr,
                                        M, 1024, 8192, nullptr, nullptr, 1, 0, nullptr);
}

// round 14
// speedup vs baseline: 1.0246x; 1.0246x over previous
#include <cuda_runtime.h>
#include <cuda_fp16.h>
#include <mma.h>
#include <cstdint>

using namespace nvcuda;

// Shapes: B=4, P=2048 -> T=8192 tokens, D=1024, H=16, KV=8, HD=64, F=4096, E=16, FE=256
#define T_TOK 8192
#define NPOS  2048

// ---------------- scratch (device globals) ----------------
__device__ __half sc_hh  [8192*1024];          // rmsnorm out (fp16)
__device__ __half sc_qkv [8192*2048];          // q|k|v packed fp16
__device__ __half sc_aoh [8192*1024];          // attention out fp16
__device__ __half sc_act [(size_t)8192*8192];  // swiglu activations fp16
__device__ float  sc_cos [2048*32];
__device__ float  sc_sin [2048*32];
__device__ float  sc_bias[2048];
__device__ __half sc_w   [28311552];           // packed fp16 weights

// packed weight offsets (elements)
#define OFF_QKV 0                 // [1024, 2048]
#define OFF_WO  2097152           // [1024, 1024]
#define OFF_GU  3145728           // [1024, 16384] col-interleaved g/u
#define OFF_DN  19922944          // [8192, 1024]

// ---------------- weight packing ----------------
__global__ __launch_bounds__(256)
void f2h_kernel(const float* __restrict__ s, __half* __restrict__ d)
{
    size_t i = ((size_t)blockIdx.x * 256 + threadIdx.x) * 8;
    float4 a = *(const float4*)(s + i);
    float4 b = *(const float4*)(s + i + 4);
    __half2 h0 = __floats2half2_rn(a.x, a.y);
    __half2 h1 = __floats2half2_rn(a.z, a.w);
    __half2 h2 = __floats2half2_rn(b.x, b.y);
    __half2 h3 = __floats2half2_rn(b.z, b.w);
    uint4 o;
    o.x = *(uint32_t*)&h0; o.y = *(uint32_t*)&h1;
    o.z = *(uint32_t*)&h2; o.w = *(uint32_t*)&h3;
    *(uint4*)(d + i) = o;
}

__global__ __launch_bounds__(256)
void pack_qkv(const float* __restrict__ wq, const float* __restrict__ wk,
              const float* __restrict__ wv, __half* __restrict__ d)
{
    int i = blockIdx.x * 256 + threadIdx.x;     // 1024*2048
    int r = i >> 11, c = i & 2047;
    float v;
    if (c < 1024)      v = wq[r * 1024 + c];
    else if (c < 1536) v = wk[r * 512 + (c - 1024)];
    else               v = wv[r * 512 + (c - 1536)];
    d[i] = __float2half(v);
}

__global__ __launch_bounds__(256)
void pack_bias(const float* __restrict__ bq, const float* __restrict__ bk,
               const float* __restrict__ bv, float* __restrict__ d)
{
    int c = blockIdx.x * 256 + threadIdx.x;     // 2048
    float v;
    if (c < 1024)      v = bq[c];
    else if (c < 1536) v = bk[c - 1024];
    else               v = bv[c - 1536];
    d[c] = v;
}

// interleaved: col 2j = gate_j, col 2j+1 = up_j ; j<4096 dense, else expert
__global__ __launch_bounds__(256)
void pack_gu(const float* __restrict__ wg, const float* __restrict__ wu,
             const float* __restrict__ eg, const float* __restrict__ eu,
             __half* __restrict__ d)
{
    size_t i = (size_t)blockIdx.x * 256 + threadIdx.x;  // 1024*16384
    int r = (int)(i >> 14), c = (int)(i & 16383);
    int j = c >> 1, up = c & 1;
    float v;
    if (j < 4096)
        v = up ? wu[(size_t)r * 4096 + j] : wg[(size_t)r * 4096 + j];
    else {
        int jj = j - 4096, e = jj >> 8, f = jj & 255;
        size_t idx = ((size_t)e * 1024 + r) * 256 + f;
        v = up ? eu[idx] : eg[idx];
    }
    d[i] = __float2half(v);
}

__global__ __launch_bounds__(256)
void pack_down(const float* __restrict__ wd, const float* __restrict__ ed,
               __half* __restrict__ d)
{
    size_t i = (size_t)blockIdx.x * 256 + threadIdx.x;  // 8192*1024
    int r = (int)(i >> 10), c = (int)(i & 1023);
    float v;
    if (r < 4096) v = wd[(size_t)r * 1024 + c];
    else {
        int r2 = r - 4096, e = r2 >> 8, f = r2 & 255;
        v = ed[((size_t)e * 256 + f) * 1024 + c];
    }
    d[i] = __float2half(v);
}

// ---------------- rmsnorm (fp32 in -> fp16 out) ----------------
__global__ __launch_bounds__(256)
void rmsnorm_kernel(const float* __restrict__ x, const float* __restrict__ w,
                    __half* __restrict__ out)
{
    int t = blockIdx.x;
    const float* xr = x + (size_t)t * 1024;
    __half* orow = out + (size_t)t * 1024;
    int tid = threadIdx.x;

    float4 v = *(const float4*)(xr + tid * 4);
    float s = v.x*v.x + v.y*v.y + v.z*v.z + v.w*v.w;
    #pragma unroll
    for (int o = 16; o; o >>= 1) s += __shfl_xor_sync(0xffffffffu, s, o);
    __shared__ float ws[8];
    if ((tid & 31) == 0) ws[tid >> 5] = s;
    __syncthreads();
    if (tid < 8) {
        float t2 = ws[tid];
        #pragma unroll
        for (int o = 4; o; o >>= 1) t2 += __shfl_xor_sync(0xffu, t2, o);
        if (tid == 0) ws[0] = t2;
    }
    __syncthreads();
    float rinv = rsqrtf(ws[0] * (1.0f / 1024.0f) + 1e-6f);
    float4 wv = *(const float4*)(w + tid * 4);
    __half2 r0 = __floats2half2_rn(v.x * rinv * wv.x, v.y * rinv * wv.y);
    __half2 r1 = __floats2half2_rn(v.z * rinv * wv.z, v.w * rinv * wv.w);
    uint2 o;
    o.x = *(uint32_t*)&r0; o.y = *(uint32_t*)&r1;
    *(uint2*)(orow + tid * 4) = o;
}

// ---------------- pipelined fp16 GEMM, 4 warps x 64x64, KC=32, 3 stages -----
// 128 thr/CTA, 3 CTAs/SM (smem 56.8KB, regs capped 170): 12 warps/SM with
// the reduced-LDSM 64x64 warp tile.
// mode 0: C/Ch = A@B (+bias/res/accum)
// mode 1 (swiglu): B col-interleaved (g,u); writes act[M, N/2] = silu(g)*u*mask
#define GBK   32
#define GLDA  40
#define GLDB  136
#define ASTG  (128 * GLDA)
#define BSTG  (GBK * GLDB)
#define NSTG  3
#define GSMEM ((NSTG * (ASTG + BSTG)) * 2)   // 56832 B -> 3 CTAs/SM

__device__ __forceinline__ void cp16(uint32_t saddr, const void* g)
{
    asm volatile("cp.async.cg.shared.global [%0], [%1], 16;\n" :: "r"(saddr), "l"(g));
}
#define CP_COMMIT() asm volatile("cp.async.commit_group;\n" ::)
#define CP_WAIT1()  asm volatile("cp.async.wait_group 1;\n" ::)
#define CP_WAIT0()  asm volatile("cp.async.wait_group 0;\n" ::)

__global__ __launch_bounds__(128, 3)
void gemm_h(const __half* __restrict__ A, const __half* __restrict__ B,
            float* __restrict__ C, __half* __restrict__ Ch,
            int M, int N, int K,
            const float* __restrict__ bias, const float* __restrict__ res,
            int accum, int swiglu, const float* __restrict__ mask)
{
    extern __shared__ __half sm[];
    __half* As = sm;
    __half* Bs = sm + NSTG * ASTG;
    uint32_t smemBase = (uint32_t)__cvta_generic_to_shared(sm);

    int bm = blockIdx.y * 128, bn = blockIdx.x * 128;
    int tid = threadIdx.x, wid = tid >> 5, lane = tid & 31;
    int wm = (wid >> 1) * 64, wn = (wid & 1) * 64;

    wmma::fragment<wmma::accumulator, 16, 16, 16, float> acc[4][4];
    #pragma unroll
    for (int i = 0; i < 4; i++)
        #pragma unroll
        for (int j = 0; j < 4; j++) wmma::fill_fragment(acc[i][j], 0.0f);

    int nk = K / GBK;

    auto prefetch = [&](int s, int k0) {
        uint32_t as = smemBase + (uint32_t)(s * ASTG) * 2;
        uint32_t bs = smemBase + (uint32_t)(NSTG * ASTG + s * BSTG) * 2;
        // A: 128 rows x 4 chunks of 8 halves = 512 chunks, 4/thread
        #pragma unroll
        for (int it = 0; it < 4; it++) {
            int j = tid + it * 128;
            int r = j >> 2, c8 = j & 3;
            cp16(as + (uint32_t)(r * GLDA + c8 * 8) * 2,
                 A + (size_t)(bm + r) * K + k0 + c8 * 8);
        }
        // B: 32 rows x 16 chunks of 8 halves = 512 chunks, 4/thread
        #pragma unroll
        for (int it = 0; it < 4; it++) {
            int j = tid + it * 128;
            int r = j >> 4, c8 = j & 15;
            cp16(bs + (uint32_t)(r * GLDB + c8 * 8) * 2,
                 B + (size_t)(k0 + r) * N + bn + c8 * 8);
        }
    };

    prefetch(0, 0);     CP_COMMIT();
    prefetch(1, GBK);   CP_COMMIT();

    for (int i = 0; i < nk; i++) {
        CP_WAIT1();
        __syncthreads();

        int s = i % NSTG;
        const __half* as = As + s * ASTG;
        const __half* bs = Bs + s * BSTG;
        #pragma unroll 1
        for (int kk = 0; kk < GBK; kk += 16) {
            wmma::fragment<wmma::matrix_a, 16, 16, 16, __half, wmma::row_major> af[4];
            #pragma unroll
            for (int ii = 0; ii < 4; ii++)
                wmma::load_matrix_sync(af[ii], as + (wm + ii * 16) * GLDA + kk, GLDA);
            #pragma unroll
            for (int jj = 0; jj < 4; jj++) {
                wmma::fragment<wmma::matrix_b, 16, 16, 16, __half, wmma::row_major> bf;
                wmma::load_matrix_sync(bf, bs + kk * GLDB + wn + jj * 16, GLDB);
                #pragma unroll
                for (int ii = 0; ii < 4; ii++)
                    wmma::mma_sync(acc[ii][jj], af[ii], bf, acc[ii][jj]);
            }
        }

        int next = i + NSTG - 1;
        if (next < nk) prefetch(next % NSTG, next * GBK);
        CP_COMMIT();
    }

    __syncthreads();

    float* buf = (float*)sm + wid * 256;
    int er = lane >> 1, ec0 = (lane & 1) * 8;   // swiglu mapping: row er, cols ec0..ec0+7
    #pragma unroll 1
    for (int i = 0; i < 4; i++)
        #pragma unroll 1
        for (int j = 0; j < 4; j++) {
            wmma::store_matrix_sync(buf, acc[i][j], 16, wmma::mem_row_major);
            __syncwarp();
            int r0 = bm + wm + i * 16, c0 = bn + wn + j * 16;
            if (swiglu) {
                // cols (even,odd) are (gate,up) pairs; act col = global_col/2
                int tok = r0 + er;
                int jb = (c0 >> 1) + (ec0 >> 1);      // 4 consecutive act cols
                float av[4];
                #pragma unroll
                for (int p = 0; p < 4; p++) {
                    float g = buf[er * 16 + ec0 + 2 * p];
                    float u = buf[er * 16 + ec0 + 2 * p + 1];
                    float a = g / (1.0f + __expf(-g)) * u;
                    int jc = jb + p;
                    if (jc >= 4096) a *= mask[(size_t)tok * 16 + ((jc - 4096) >> 8)];
                    av[p] = a;
                }
                __half2 h01 = __floats2half2_rn(av[0], av[1]);
                __half2 h23 = __floats2half2_rn(av[2], av[3]);
                uint2 o; o.x = *(uint32_t*)&h01; o.y = *(uint32_t*)&h23;
                *(uint2*)(Ch + (size_t)tok * (N >> 1) + jb) = o;
            } else {
                #pragma unroll
                for (int t2 = 0; t2 < 8; t2++) {
                    int e = lane * 8 + t2;
                    int rr = e >> 4, cc = e & 15;
                    float vv = buf[e];
                    if (bias) vv += bias[c0 + cc];
                    size_t ci = (size_t)(r0 + rr) * N + (c0 + cc);
                    if (res)   vv += res[ci];
                    if (accum) vv += C[ci];
                    if (Ch) Ch[ci] = __float2half(vv);
                    else    C[ci]  = vv;
                }
            }
            __syncwarp();
        }
}

// ---------------- RoPE ----------------
__global__ void rope_table(float* __restrict__ ct, float* __restrict__ st)
{
    int i = blockIdx.x * 256 + threadIdx.x;
    int p = i >> 5, j = i & 31;
    float inv = powf(10000.0f, -(float)j * (1.0f / 32.0f));
    float ang = (float)p * inv;
    float s, c;
    sincosf(ang, &s, &c);
    ct[i] = c; st[i] = s;
}

// q (16 heads, col 0) and k (8 heads, col 1024) in one launch
__global__ void rope_apply(__half* __restrict__ qkv,
                           const float* __restrict__ ct, const float* __restrict__ st)
{
    int i = blockIdx.x * 256 + threadIdx.x;      // T*24*32 total
    int j = i & 31;
    int hh = (i >> 5) % 24;
    int t = i / (24 * 32);
    int p = t & (NPOS - 1);
    int coff = (hh < 16) ? (hh * 64) : (1024 + (hh - 16) * 64);
    float c = ct[p * 32 + j], s = st[p * 32 + j];
    size_t base = (size_t)t * 2048 + coff;
    float v1 = __half2float(qkv[base + j]);
    float v2 = __half2float(qkv[base + 32 + j]);
    qkv[base + j]      = __float2half(v1 * c - v2 * s);
    qkv[base + 32 + j] = __float2half(v2 * c + v1 * s);
}

// ---------------- fp16 flash attention (causal, GQA 2:1, HD=64, 64-row) ------
#define FLD 72
#define FT  4608
#define FLASH_SMEM ((6 * FT) * 2 + (2 * FT + 192) * 4)
__global__ __launch_bounds__(256)
void flash16(const __half* __restrict__ qkv, __half* __restrict__ o)
{
    extern __shared__ __half smh[];
    __half* Qs = smh;
    __half* Ks = Qs + FT;
    __half* Vs = Ks + 2 * FT;
    __half* Ps = Vs + 2 * FT;
    float*  Ss = (float*)(Ps + FT);
    float*  Os = Ss + FT;
    float*  mrow = Os + FT;
    float*  lrow = mrow + 64;
    float*  crow = lrow + 64;
    uint32_t smemBase = (uint32_t)__cvta_generic_to_shared(smh);

    int qt = blockIdx.x, h = blockIdx.y, b = blockIdx.z;
    int tid = threadIdx.x, wid = tid >> 5;
    int kvh = h >> 1;

    const __half* qb = qkv + ((size_t)(b * NPOS + qt * 64)) * 2048 + h * 64;
    const __half2 sc8 = __floats2half2_rn(0.125f, 0.125f);
    for (int it = 0; it < 2; it++) {
        int j = tid + it * 256;
        int r = j >> 3, c8 = j & 7;
        uint4 raw = *(const uint4*)(qb + (size_t)r * 2048 + c8 * 8);
        __half2* hp = (__half2*)&raw;
        #pragma unroll
        for (int q2 = 0; q2 < 4; q2++) hp[q2] = __hmul2(hp[q2], sc8);
        *(uint4*)(Qs + r * FLD + c8 * 8) = raw;
    }
    for (int i = tid; i < 4096; i += 256) {
        int r = i >> 6, c = i & 63;
        Os[r * FLD + c] = 0.0f;
    }
    if (tid < 64) { mrow[tid] = -1e30f; lrow[tid] = 0.0f; }

    auto pf = [&](int kt, int bi) {
        const __half* kb = qkv + ((size_t)(b * NPOS + kt * 64)) * 2048 + 1024 + kvh * 64;
        uint32_t ks = smemBase + (uint32_t)(FT + bi * FT) * 2;
        uint32_t vs = smemBase + (uint32_t)(3 * FT + bi * FT) * 2;
        #pragma unroll
        for (int it = 0; it < 2; it++) {
            int j = tid + it * 256;
            int r = j >> 3, c8 = j & 7;
            cp16(ks + (uint32_t)(r * FLD + c8 * 8) * 2, kb + (size_t)r * 2048 + c8 * 8);
            cp16(vs + (uint32_t)(r * FLD + c8 * 8) * 2, kb + (size_t)r * 2048 + 512 + c8 * 8);
        }
    };

    pf(0, 0);
    CP_COMMIT();
    __syncthreads();

    int wm = (wid >> 1) * 16, wn = (wid & 1) * 32;

    for (int kt = 0; kt <= qt; kt++) {
        int bi = kt & 1;
        CP_WAIT0();
        __syncthreads();
        if (kt < qt) pf(kt + 1, bi ^ 1);
        CP_COMMIT();

        const __half* kcur = Ks + bi * FT;
        const __half* vcur = Vs + bi * FT;

        {
            wmma::fragment<wmma::accumulator, 16, 16, 16, float> sa[2];
            wmma::fill_fragment(sa[0], 0.0f);
            wmma::fill_fragment(sa[1], 0.0f);
            #pragma unroll
            for (int d = 0; d < 64; d += 16) {
                wmma::fragment<wmma::matrix_a, 16, 16, 16, __half, wmma::row_major> af;
                wmma::load_matrix_sync(af, Qs + wm * FLD + d, FLD);
                #pragma unroll
                for (int jj = 0; jj < 2; jj++) {
                    wmma::fragment<wmma::matrix_b, 16, 16, 16, __half, wmma::col_major> bf;
                    wmma::load_matrix_sync(bf, kcur + (wn + jj * 16) * FLD + d, FLD);
                    wmma::mma_sync(sa[jj], af, bf, sa[jj]);
                }
            }
            wmma::store_matrix_sync(Ss + wm * FLD + wn,      sa[0], FLD, wmma::mem_row_major);
            wmma::store_matrix_sync(Ss + wm * FLD + wn + 16, sa[1], FLD, wmma::mem_row_major);
        }
        __syncthreads();

        {
            int r = tid >> 2, pp = tid & 3;
            int qg = qt * 64 + r;
            float vals[16]; float mx = -1e30f;
            #pragma unroll
            for (int c = 0; c < 16; c++) {
                int col = pp * 16 + c;
                float sv = Ss[r * FLD + col];
                if (kt * 64 + col > qg) sv = -1e30f;
                vals[c] = sv; mx = fmaxf(mx, sv);
            }
            mx = fmaxf(mx, __shfl_xor_sync(0xffffffffu, mx, 1));
            mx = fmaxf(mx, __shfl_xor_sync(0xffffffffu, mx, 2));
            float mold = mrow[r];
            float mnew = fmaxf(mold, mx);
            float sum = 0.0f;
            #pragma unroll
            for (int c = 0; c < 16; c++) {
                float e = __expf(vals[c] - mnew);
                Ps[r * FLD + pp * 16 + c] = __float2half(e);
                sum += e;
            }
            sum += __shfl_xor_sync(0xffffffffu, sum, 1);
            sum += __shfl_xor_sync(0xffffffffu, sum, 2);
            if (pp == 0) {
                float cc = __expf(mold - mnew);
                lrow[r] = lrow[r] * cc + sum;
                mrow[r] = mnew;
                crow[r] = cc;
            }
        }
        __syncthreads();

        {
            wmma::fragment<wmma::accumulator, 16, 16, 16, float> pv[2];
            wmma::fill_fragment(pv[0], 0.0f);
            wmma::fill_fragment(pv[1], 0.0f);
            #pragma unroll
            for (int kk = 0; kk < 64; kk += 16) {
                wmma::fragment<wmma::matrix_a, 16, 16, 16, __half, wmma::row_major> af;
                wmma::load_matrix_sync(af, Ps + wm * FLD + kk, FLD);
                #pragma unroll
                for (int jj = 0; jj < 2; jj++) {
                    wmma::fragment<wmma::matrix_b, 16, 16, 16, __half, wmma::row_major> bf;
                    wmma::load_matrix_sync(bf, vcur + kk * FLD + wn + jj * 16, FLD);
                    wmma::mma_sync(pv[jj], af, bf, pv[jj]);
                }
            }
            wmma::store_matrix_sync(Ss + wm * FLD + wn,      pv[0], FLD, wmma::mem_row_major);
            wmma::store_matrix_sync(Ss + wm * FLD + wn + 16, pv[1], FLD, wmma::mem_row_major);
        }
        __syncthreads();

        for (int i = tid; i < 4096; i += 256) {
            int r = i >> 6, c = i & 63;
            Os[r * FLD + c] = Os[r * FLD + c] * crow[r] + Ss[r * FLD + c];
        }
        __syncthreads();
    }

    __half* ob = o + ((size_t)(b * NPOS + qt * 64)) * 1024 + h * 64;
    for (int i = tid; i < 4096; i += 256) {
        int r = i >> 6, c = i & 63;
        ob[(size_t)r * 1024 + c] = __float2half(Os[r * FLD + c] / lrow[r]);
    }
}

// ---------------- launch ----------------
extern "C" void kernel_launch(void* const* d_in, const int* in_sizes, int n_in,
                              void* d_out, int out_size)
{
    const float* x       = (const float*)d_in[0];
    const float* emask   = (const float*)d_in[1];
    const float* ln1     = (const float*)d_in[2];
    const float* wq      = (const float*)d_in[3];
    const float* bq      = (const float*)d_in[4];
    const float* wk      = (const float*)d_in[5];
    const float* bk      = (const float*)d_in[6];
    const float* wv      = (const float*)d_in[7];
    const float* bv      = (const float*)d_in[8];
    const float* wo      = (const float*)d_in[9];
    const float* ln2     = (const float*)d_in[10];
    const float* w_gate  = (const float*)d_in[11];
    const float* w_up    = (const float*)d_in[12];
    const float* w_down  = (const float*)d_in[13];
    const float* we_gate = (const float*)d_in[14];
    const float* we_up   = (const float*)d_in[15];
    const float* we_down = (const float*)d_in[16];
    float* out = (float*)d_out;

    __half *hh, *qkv, *aoh, *act, *w;
    float *ct, *st, *bias;
    cudaGetSymbolAddress((void**)&hh,   sc_hh);
    cudaGetSymbolAddress((void**)&qkv,  sc_qkv);
    cudaGetSymbolAddress((void**)&aoh,  sc_aoh);
    cudaGetSymbolAddress((void**)&act,  sc_act);
    cudaGetSymbolAddress((void**)&w,    sc_w);
    cudaGetSymbolAddress((void**)&ct,   sc_cos);
    cudaGetSymbolAddress((void**)&st,   sc_sin);
    cudaGetSymbolAddress((void**)&bias, sc_bias);

    cudaFuncSetAttribute(flash16, cudaFuncAttributeMaxDynamicSharedMemorySize, FLASH_SMEM);
    cudaFuncSetAttribute(gemm_h, cudaFuncAttributeMaxDynamicSharedMemorySize, GSMEM);

    const int M = T_TOK;
    dim3 thr(128);

    // early ordering so the ncu capture index lands on a GEMM launch
    pack_bias<<<8, 256>>>(bq, bk, bv, bias);
    pack_qkv<<<8192, 256>>>(wq, wk, wv, w + OFF_QKV);
    rmsnorm_kernel<<<M, 256>>>(x, ln1, hh);

    // launch #4: QKV projection (bias folded)
    gemm_h<<<dim3(16, 64), thr, GSMEM>>>(hh, w + OFF_QKV, nullptr, qkv,
                                         M, 2048, 1024, bias, nullptr, 0, 0, nullptr);

    pack_gu<<<65536, 256>>>(w_gate, w_up, we_gate, we_up, w + OFF_GU);
    f2h_kernel<<<512, 256>>>(wo, w + OFF_WO);
    pack_down<<<32768, 256>>>(w_down, we_down, w + OFF_DN);
    rope_table<<<256, 256>>>(ct, st);
    rope_apply<<<24576, 256>>>(qkv, ct, st);

    flash16<<<dim3(32, 16, 4), 256, FLASH_SMEM>>>(qkv, aoh);

    // out = x + attn @ Wo
    gemm_h<<<dim3(8, 64), thr, GSMEM>>>(aoh, w + OFF_WO, out, nullptr,
                                        M, 1024, 1024, nullptr, x, 0, 0, nullptr);

    rmsnorm_kernel<<<M, 256>>>(out, ln2, hh);

    // fused gate|up (+experts) GEMM with swiglu epilogue -> act[T, 8192]
    gemm_h<<<dim3(128, 64), thr, GSMEM>>>(hh, w + OFF_GU, nullptr, act,
                                          M, 16384, 1024, nullptr, nullptr, 0, 1, emask);

    // fused down: out += act @ [Wd ; Ed]
    gemm_h<<<dim3(8, 64), thr, GSMEM>>>(act, w + OFF_DN, out, nullptr,
                                        M, 1024, 8192, nullptr, nullptr, 1, 0, nullptr);
}

// round 15
// speedup vs baseline: 1.0504x; 1.0252x over previous
#include <cuda_runtime.h>
#include <cuda_fp16.h>
#include <mma.h>
#include <cstdint>

using namespace nvcuda;

// Shapes: B=4, P=2048 -> T=8192 tokens, D=1024, H=16, KV=8, HD=64, F=4096, E=16, FE=256
#define T_TOK 8192
#define NPOS  2048

// ---------------- scratch (device globals) ----------------
__device__ __half sc_hh  [8192*1024];          // rmsnorm out (fp16)
__device__ __half sc_qkv [8192*2048];          // q|k|v packed fp16
__device__ __half sc_aoh [8192*1024];          // attention out fp16
__device__ __half sc_act [(size_t)8192*8192];  // swiglu activations fp16
__device__ float  sc_cos [2048*32];
__device__ float  sc_sin [2048*32];
__device__ float  sc_bias[2048];
__device__ __half sc_w   [28311552];           // packed fp16 weights

// packed weight offsets (elements)
#define OFF_QKV 0                 // [1024, 2048]  (q-cols pre-scaled by 1/8)
#define OFF_WO  2097152           // [1024, 1024]
#define OFF_GU  3145728           // [1024, 16384] col-interleaved g/u
#define OFF_DN  19922944          // [8192, 1024]

// ---------------- weight packing ----------------
__global__ __launch_bounds__(256)
void f2h_kernel(const float* __restrict__ s, __half* __restrict__ d)
{
    size_t i = ((size_t)blockIdx.x * 256 + threadIdx.x) * 8;
    float4 a = *(const float4*)(s + i);
    float4 b = *(const float4*)(s + i + 4);
    __half2 h0 = __floats2half2_rn(a.x, a.y);
    __half2 h1 = __floats2half2_rn(a.z, a.w);
    __half2 h2 = __floats2half2_rn(b.x, b.y);
    __half2 h3 = __floats2half2_rn(b.z, b.w);
    uint4 o;
    o.x = *(uint32_t*)&h0; o.y = *(uint32_t*)&h1;
    o.z = *(uint32_t*)&h2; o.w = *(uint32_t*)&h3;
    *(uint4*)(d + i) = o;
}

// 4 elems/thread; q-region (c<1024) folded by 0.125 (attention 1/sqrt(64) scale)
__global__ __launch_bounds__(256)
void pack_qkv(const float* __restrict__ wq, const float* __restrict__ wk,
              const float* __restrict__ wv, __half* __restrict__ d)
{
    int i = (blockIdx.x * 256 + threadIdx.x) * 4;   // 1024*2048 elems
    int r = i >> 11, c = i & 2047;
    float4 v;
    float sc = 1.0f;
    if (c < 1024)      { v = *(const float4*)(wq + (size_t)r * 1024 + c); sc = 0.125f; }
    else if (c < 1536)   v = *(const float4*)(wk + (size_t)r * 512 + (c - 1024));
    else                 v = *(const float4*)(wv + (size_t)r * 512 + (c - 1536));
    __half2 h0 = __floats2half2_rn(v.x * sc, v.y * sc);
    __half2 h1 = __floats2half2_rn(v.z * sc, v.w * sc);
    uint2 o; o.x = *(uint32_t*)&h0; o.y = *(uint32_t*)&h1;
    *(uint2*)(d + i) = o;
}

__global__ __launch_bounds__(256)
void pack_bias(const float* __restrict__ bq, const float* __restrict__ bk,
               const float* __restrict__ bv, float* __restrict__ d)
{
    int c = blockIdx.x * 256 + threadIdx.x;     // 2048
    float v;
    if (c < 1024)      v = bq[c] * 0.125f;
    else if (c < 1536) v = bk[c - 1024];
    else               v = bv[c - 1536];
    d[c] = v;
}

// one (gate,up) pair per thread: stride-1 reads on both sources, 32-bit write
__global__ __launch_bounds__(256)
void pack_gu(const float* __restrict__ wg, const float* __restrict__ wu,
             const float* __restrict__ eg, const float* __restrict__ eu,
             __half* __restrict__ d)
{
    size_t p = (size_t)blockIdx.x * 256 + threadIdx.x;  // 1024*8192 pairs
    int r = (int)(p >> 13), j = (int)(p & 8191);
    float g, u;
    if (j < 4096) {
        g = wg[(size_t)r * 4096 + j];
        u = wu[(size_t)r * 4096 + j];
    } else {
        int jj = j - 4096, e = jj >> 8, f = jj & 255;
        size_t idx = ((size_t)e * 1024 + r) * 256 + f;
        g = eg[idx];
        u = eu[idx];
    }
    __half2 h = __floats2half2_rn(g, u);
    *(uint32_t*)(d + p * 2) = *(uint32_t*)&h;
}

// 8 elems/thread, rows are 1024-contiguous in both sources
__global__ __launch_bounds__(256)
void pack_down(const float* __restrict__ wd, const float* __restrict__ ed,
               __half* __restrict__ d)
{
    size_t i = ((size_t)blockIdx.x * 256 + threadIdx.x) * 8;  // 8192*1024 elems
    int r = (int)(i >> 10), c = (int)(i & 1023);
    const float* src;
    if (r < 4096) src = wd + (size_t)r * 1024 + c;
    else {
        int r2 = r - 4096, e = r2 >> 8, f = r2 & 255;
        src = ed + ((size_t)e * 256 + f) * 1024 + c;
    }
    float4 a = *(const float4*)(src);
    float4 b = *(const float4*)(src + 4);
    __half2 h0 = __floats2half2_rn(a.x, a.y);
    __half2 h1 = __floats2half2_rn(a.z, a.w);
    __half2 h2 = __floats2half2_rn(b.x, b.y);
    __half2 h3 = __floats2half2_rn(b.z, b.w);
    uint4 o;
    o.x = *(uint32_t*)&h0; o.y = *(uint32_t*)&h1;
    o.z = *(uint32_t*)&h2; o.w = *(uint32_t*)&h3;
    *(uint4*)(d + i) = o;
}

// ---------------- rmsnorm (fp32 in -> fp16 out) ----------------
__global__ __launch_bounds__(256)
void rmsnorm_kernel(const float* __restrict__ x, const float* __restrict__ w,
                    __half* __restrict__ out)
{
    int t = blockIdx.x;
    const float* xr = x + (size_t)t * 1024;
    __half* orow = out + (size_t)t * 1024;
    int tid = threadIdx.x;

    float4 v = *(const float4*)(xr + tid * 4);
    float s = v.x*v.x + v.y*v.y + v.z*v.z + v.w*v.w;
    #pragma unroll
    for (int o = 16; o; o >>= 1) s += __shfl_xor_sync(0xffffffffu, s, o);
    __shared__ float ws[8];
    if ((tid & 31) == 0) ws[tid >> 5] = s;
    __syncthreads();
    if (tid < 8) {
        float t2 = ws[tid];
        #pragma unroll
        for (int o = 4; o; o >>= 1) t2 += __shfl_xor_sync(0xffu, t2, o);
        if (tid == 0) ws[0] = t2;
    }
    __syncthreads();
    float rinv = rsqrtf(ws[0] * (1.0f / 1024.0f) + 1e-6f);
    float4 wv = *(const float4*)(w + tid * 4);
    __half2 r0 = __floats2half2_rn(v.x * rinv * wv.x, v.y * rinv * wv.y);
    __half2 r1 = __floats2half2_rn(v.z * rinv * wv.z, v.w * rinv * wv.w);
    uint2 o;
    o.x = *(uint32_t*)&r0; o.y = *(uint32_t*)&r1;
    *(uint2*)(orow + tid * 4) = o;
}

// ---------------- pipelined fp16 GEMM, 4 warps x 64x64, KC=32, 3 stages -----
// (round-14 best config: 128 thr/CTA, 3 CTAs/SM, regs<=170)
#define GBK   32
#define GLDA  40
#define GLDB  136
#define ASTG  (128 * GLDA)
#define BSTG  (GBK * GLDB)
#define NSTG  3
#define GSMEM ((NSTG * (ASTG + BSTG)) * 2)   // 56832 B -> 3 CTAs/SM

__device__ __forceinline__ void cp16(uint32_t saddr, const void* g)
{
    asm volatile("cp.async.cg.shared.global [%0], [%1], 16;\n" :: "r"(saddr), "l"(g));
}
#define CP_COMMIT() asm volatile("cp.async.commit_group;\n" ::)
#define CP_WAIT1()  asm volatile("cp.async.wait_group 1;\n" ::)
#define CP_WAIT0()  asm volatile("cp.async.wait_group 0;\n" ::)

__global__ __launch_bounds__(128, 3)
void gemm_h(const __half* __restrict__ A, const __half* __restrict__ B,
            float* __restrict__ C, __half* __restrict__ Ch,
            int M, int N, int K,
            const float* __restrict__ bias, const float* __restrict__ res,
            int accum, int swiglu, const float* __restrict__ mask)
{
    extern __shared__ __half sm[];
    __half* As = sm;
    __half* Bs = sm + NSTG * ASTG;
    uint32_t smemBase = (uint32_t)__cvta_generic_to_shared(sm);

    int bm = blockIdx.y * 128, bn = blockIdx.x * 128;
    int tid = threadIdx.x, wid = tid >> 5, lane = tid & 31;
    int wm = (wid >> 1) * 64, wn = (wid & 1) * 64;

    wmma::fragment<wmma::accumulator, 16, 16, 16, float> acc[4][4];
    #pragma unroll
    for (int i = 0; i < 4; i++)
        #pragma unroll
        for (int j = 0; j < 4; j++) wmma::fill_fragment(acc[i][j], 0.0f);

    int nk = K / GBK;

    auto prefetch = [&](int s, int k0) {
        uint32_t as = smemBase + (uint32_t)(s * ASTG) * 2;
        uint32_t bs = smemBase + (uint32_t)(NSTG * ASTG + s * BSTG) * 2;
        #pragma unroll
        for (int it = 0; it < 4; it++) {
            int j = tid + it * 128;
            int r = j >> 2, c8 = j & 3;
            cp16(as + (uint32_t)(r * GLDA + c8 * 8) * 2,
                 A + (size_t)(bm + r) * K + k0 + c8 * 8);
        }
        #pragma unroll
        for (int it = 0; it < 4; it++) {
            int j = tid + it * 128;
            int r = j >> 4, c8 = j & 15;
            cp16(bs + (uint32_t)(r * GLDB + c8 * 8) * 2,
                 B + (size_t)(k0 + r) * N + bn + c8 * 8);
        }
    };

    prefetch(0, 0);     CP_COMMIT();
    prefetch(1, GBK);   CP_COMMIT();

    for (int i = 0; i < nk; i++) {
        CP_WAIT1();
        __syncthreads();

        int s = i % NSTG;
        const __half* as = As + s * ASTG;
        const __half* bs = Bs + s * BSTG;
        #pragma unroll 1
        for (int kk = 0; kk < GBK; kk += 16) {
            wmma::fragment<wmma::matrix_a, 16, 16, 16, __half, wmma::row_major> af[4];
            #pragma unroll
            for (int ii = 0; ii < 4; ii++)
                wmma::load_matrix_sync(af[ii], as + (wm + ii * 16) * GLDA + kk, GLDA);
            #pragma unroll
            for (int jj = 0; jj < 4; jj++) {
                wmma::fragment<wmma::matrix_b, 16, 16, 16, __half, wmma::row_major> bf;
                wmma::load_matrix_sync(bf, bs + kk * GLDB + wn + jj * 16, GLDB);
                #pragma unroll
                for (int ii = 0; ii < 4; ii++)
                    wmma::mma_sync(acc[ii][jj], af[ii], bf, acc[ii][jj]);
            }
        }

        int next = i + NSTG - 1;
        if (next < nk) prefetch(next % NSTG, next * GBK);
        CP_COMMIT();
    }

    __syncthreads();

    float* buf = (float*)sm + wid * 256;
    int er = lane >> 1, ec0 = (lane & 1) * 8;
    #pragma unroll 1
    for (int i = 0; i < 4; i++)
        #pragma unroll 1
        for (int j = 0; j < 4; j++) {
            wmma::store_matrix_sync(buf, acc[i][j], 16, wmma::mem_row_major);
            __syncwarp();
            int r0 = bm + wm + i * 16, c0 = bn + wn + j * 16;
            if (swiglu) {
                int tok = r0 + er;
                int jb = (c0 >> 1) + (ec0 >> 1);
                float av[4];
                #pragma unroll
                for (int p = 0; p < 4; p++) {
                    float g = buf[er * 16 + ec0 + 2 * p];
                    float u = buf[er * 16 + ec0 + 2 * p + 1];
                    float a = g / (1.0f + __expf(-g)) * u;
                    int jc = jb + p;
                    if (jc >= 4096) a *= mask[(size_t)tok * 16 + ((jc - 4096) >> 8)];
                    av[p] = a;
                }
                __half2 h01 = __floats2half2_rn(av[0], av[1]);
                __half2 h23 = __floats2half2_rn(av[2], av[3]);
                uint2 o; o.x = *(uint32_t*)&h01; o.y = *(uint32_t*)&h23;
                *(uint2*)(Ch + (size_t)tok * (N >> 1) + jb) = o;
            } else {
                #pragma unroll
                for (int t2 = 0; t2 < 8; t2++) {
                    int e = lane * 8 + t2;
                    int rr = e >> 4, cc = e & 15;
                    float vv = buf[e];
                    if (bias) vv += bias[c0 + cc];
                    size_t ci = (size_t)(r0 + rr) * N + (c0 + cc);
                    if (res)   vv += res[ci];
                    if (accum) vv += C[ci];
                    if (Ch) Ch[ci] = __float2half(vv);
                    else    C[ci]  = vv;
                }
            }
            __syncwarp();
        }
}

// ---------------- RoPE ----------------
__global__ void rope_table(float* __restrict__ ct, float* __restrict__ st)
{
    int i = blockIdx.x * 256 + threadIdx.x;
    int p = i >> 5, j = i & 31;
    float inv = powf(10000.0f, -(float)j * (1.0f / 32.0f));
    float ang = (float)p * inv;
    float s, c;
    sincosf(ang, &s, &c);
    ct[i] = c; st[i] = s;
}

__global__ void rope_apply(__half* __restrict__ qkv,
                           const float* __restrict__ ct, const float* __restrict__ st)
{
    int i = blockIdx.x * 256 + threadIdx.x;      // T*24*32 total
    int j = i & 31;
    int hh = (i >> 5) % 24;
    int t = i / (24 * 32);
    int p = t & (NPOS - 1);
    int coff = (hh < 16) ? (hh * 64) : (1024 + (hh - 16) * 64);
    float c = ct[p * 32 + j], s = st[p * 32 + j];
    size_t base = (size_t)t * 2048 + coff;
    float v1 = __half2float(qkv[base + j]);
    float v2 = __half2float(qkv[base + 32 + j]);
    qkv[base + j]      = __float2half(v1 * c - v2 * s);
    qkv[base + 32 + j] = __float2half(v2 * c + v1 * s);
}

// ---------------- fp16 flash attention (causal, GQA 2:1, HD=64, 64-row) ------
// Q already pre-scaled by 1/8 (folded into Wq/bq). Heaviest qt launched first.
#define FLD 72
#define FT  4608
#define FLASH_SMEM ((6 * FT) * 2 + (2 * FT + 192) * 4)
__global__ __launch_bounds__(256)
void flash16(const __half* __restrict__ qkv, __half* __restrict__ o)
{
    extern __shared__ __half smh[];
    __half* Qs = smh;
    __half* Ks = Qs + FT;
    __half* Vs = Ks + 2 * FT;
    __half* Ps = Vs + 2 * FT;
    float*  Ss = (float*)(Ps + FT);
    float*  Os = Ss + FT;
    float*  mrow = Os + FT;
    float*  lrow = mrow + 64;
    float*  crow = lrow + 64;
    uint32_t smemBase = (uint32_t)__cvta_generic_to_shared(smh);

    int qt = gridDim.x - 1 - blockIdx.x;   // heaviest blocks first
    int h = blockIdx.y, b = blockIdx.z;
    int tid = threadIdx.x, wid = tid >> 5;
    int kvh = h >> 1;

    const __half* qb = qkv + ((size_t)(b * NPOS + qt * 64)) * 2048 + h * 64;
    for (int it = 0; it < 2; it++) {
        int j = tid + it * 256;
        int r = j >> 3, c8 = j & 7;
        *(uint4*)(Qs + r * FLD + c8 * 8) = *(const uint4*)(qb + (size_t)r * 2048 + c8 * 8);
    }
    for (int i = tid; i < 4096; i += 256) {
        int r = i >> 6, c = i & 63;
        Os[r * FLD + c] = 0.0f;
    }
    if (tid < 64) { mrow[tid] = -1e30f; lrow[tid] = 0.0f; }

    auto pf = [&](int kt, int bi) {
        const __half* kb = qkv + ((size_t)(b * NPOS + kt * 64)) * 2048 + 1024 + kvh * 64;
        uint32_t ks = smemBase + (uint32_t)(FT + bi * FT) * 2;
        uint32_t vs = smemBase + (uint32_t)(3 * FT + bi * FT) * 2;
        #pragma unroll
        for (int it = 0; it < 2; it++) {
            int j = tid + it * 256;
            int r = j >> 3, c8 = j & 7;
            cp16(ks + (uint32_t)(r * FLD + c8 * 8) * 2, kb + (size_t)r * 2048 + c8 * 8);
            cp16(vs + (uint32_t)(r * FLD + c8 * 8) * 2, kb + (size_t)r * 2048 + 512 + c8 * 8);
        }
    };

    pf(0, 0);
    CP_COMMIT();
    __syncthreads();

    int wm = (wid >> 1) * 16, wn = (wid & 1) * 32;

    for (int kt = 0; kt <= qt; kt++) {
        int bi = kt & 1;
        CP_WAIT0();
        __syncthreads();
        if (kt < qt) pf(kt + 1, bi ^ 1);
        CP_COMMIT();

        const __half* kcur = Ks + bi * FT;
        const __half* vcur = Vs + bi * FT;

        {
            wmma::fragment<wmma::accumulator, 16, 16, 16, float> sa[2];
            wmma::fill_fragment(sa[0], 0.0f);
            wmma::fill_fragment(sa[1], 0.0f);
            #pragma unroll
            for (int d = 0; d < 64; d += 16) {
                wmma::fragment<wmma::matrix_a, 16, 16, 16, __half, wmma::row_major> af;
                wmma::load_matrix_sync(af, Qs + wm * FLD + d, FLD);
                #pragma unroll
                for (int jj = 0; jj < 2; jj++) {
                    wmma::fragment<wmma::matrix_b, 16, 16, 16, __half, wmma::col_major> bf;
                    wmma::load_matrix_sync(bf, kcur + (wn + jj * 16) * FLD + d, FLD);
                    wmma::mma_sync(sa[jj], af, bf, sa[jj]);
                }
            }
            wmma::store_matrix_sync(Ss + wm * FLD + wn,      sa[0], FLD, wmma::mem_row_major);
            wmma::store_matrix_sync(Ss + wm * FLD + wn + 16, sa[1], FLD, wmma::mem_row_major);
        }
        __syncthreads();

        {
            int r = tid >> 2, pp = tid & 3;
            int qg = qt * 64 + r;
            float vals[16]; float mx = -1e30f;
            #pragma unroll
            for (int c = 0; c < 16; c++) {
                int col = pp * 16 + c;
                float sv = Ss[r * FLD + col];
                if (kt * 64 + col > qg) sv = -1e30f;
                vals[c] = sv; mx = fmaxf(mx, sv);
            }
            mx = fmaxf(mx, __shfl_xor_sync(0xffffffffu, mx, 1));
            mx = fmaxf(mx, __shfl_xor_sync(0xffffffffu, mx, 2));
            float mold = mrow[r];
            float mnew = fmaxf(mold, mx);
            float sum = 0.0f;
            #pragma unroll
            for (int c = 0; c < 16; c++) {
                float e = __expf(vals[c] - mnew);
                Ps[r * FLD + pp * 16 + c] = __float2half(e);
                sum += e;
            }
            sum += __shfl_xor_sync(0xffffffffu, sum, 1);
            sum += __shfl_xor_sync(0xffffffffu, sum, 2);
            if (pp == 0) {
                float cc = __expf(mold - mnew);
                lrow[r] = lrow[r] * cc + sum;
                mrow[r] = mnew;
                crow[r] = cc;
            }
        }
        __syncthreads();

        {
            wmma::fragment<wmma::accumulator, 16, 16, 16, float> pv[2];
            wmma::fill_fragment(pv[0], 0.0f);
            wmma::fill_fragment(pv[1], 0.0f);
            #pragma unroll
            for (int kk = 0; kk < 64; kk += 16) {
                wmma::fragment<wmma::matrix_a, 16, 16, 16, __half, wmma::row_major> af;
                wmma::load_matrix_sync(af, Ps + wm * FLD + kk, FLD);
                #pragma unroll
                for (int jj = 0; jj < 2; jj++) {
                    wmma::fragment<wmma::matrix_b, 16, 16, 16, __half, wmma::row_major> bf;
                    wmma::load_matrix_sync(bf, vcur + kk * FLD + wn + jj * 16, FLD);
                    wmma::mma_sync(pv[jj], af, bf, pv[jj]);
                }
            }
            wmma::store_matrix_sync(Ss + wm * FLD + wn,      pv[0], FLD, wmma::mem_row_major);
            wmma::store_matrix_sync(Ss + wm * FLD + wn + 16, pv[1], FLD, wmma::mem_row_major);
        }
        __syncthreads();

        for (int i = tid; i < 4096; i += 256) {
            int r = i >> 6, c = i & 63;
            Os[r * FLD + c] = Os[r * FLD + c] * crow[r] + Ss[r * FLD + c];
        }
        __syncthreads();
    }

    __half* ob = o + ((size_t)(b * NPOS + qt * 64)) * 1024 + h * 64;
    for (int i = tid; i < 4096; i += 256) {
        int r = i >> 6, c = i & 63;
        ob[(size_t)r * 1024 + c] = __float2half(Os[r * FLD + c] / lrow[r]);
    }
}

// ---------------- launch ----------------
extern "C" void kernel_launch(void* const* d_in, const int* in_sizes, int n_in,
                              void* d_out, int out_size)
{
    const float* x       = (const float*)d_in[0];
    const float* emask   = (const float*)d_in[1];
    const float* ln1     = (const float*)d_in[2];
    const float* wq      = (const float*)d_in[3];
    const float* bq      = (const float*)d_in[4];
    const float* wk      = (const float*)d_in[5];
    const float* bk      = (const float*)d_in[6];
    const float* wv      = (const float*)d_in[7];
    const float* bv      = (const float*)d_in[8];
    const float* wo      = (const float*)d_in[9];
    const float* ln2     = (const float*)d_in[10];
    const float* w_gate  = (const float*)d_in[11];
    const float* w_up    = (const float*)d_in[12];
    const float* w_down  = (const float*)d_in[13];
    const float* we_gate = (const float*)d_in[14];
    const float* we_up   = (const float*)d_in[15];
    const float* we_down = (const float*)d_in[16];
    float* out = (float*)d_out;

    __half *hh, *qkv, *aoh, *act, *w;
    float *ct, *st, *bias;
    cudaGetSymbolAddress((void**)&hh,   sc_hh);
    cudaGetSymbolAddress((void**)&qkv,  sc_qkv);
    cudaGetSymbolAddress((void**)&aoh,  sc_aoh);
    cudaGetSymbolAddress((void**)&act,  sc_act);
    cudaGetSymbolAddress((void**)&w,    sc_w);
    cudaGetSymbolAddress((void**)&ct,   sc_cos);
    cudaGetSymbolAddress((void**)&st,   sc_sin);
    cudaGetSymbolAddress((void**)&bias, sc_bias);

    cudaFuncSetAttribute(flash16, cudaFuncAttributeMaxDynamicSharedMemorySize, FLASH_SMEM);
    cudaFuncSetAttribute(gemm_h, cudaFuncAttributeMaxDynamicSharedMemorySize, GSMEM);

    const int M = T_TOK;
    dim3 thr(128);

    // fork: big weight packs run on a side stream, hidden under qkv/rope/flash
    cudaStream_t s1;
    cudaStreamCreate(&s1);
    cudaEvent_t e0, e1;
    cudaEventCreateWithFlags(&e0, cudaEventDisableTiming);
    cudaEventCreateWithFlags(&e1, cudaEventDisableTiming);
    cudaEventRecord(e0, 0);
    cudaStreamWaitEvent(s1, e0, 0);
    pack_gu<<<32768, 256, 0, s1>>>(w_gate, w_up, we_gate, we_up, w + OFF_GU);
    pack_down<<<4096, 256, 0, s1>>>(w_down, we_down, w + OFF_DN);
    f2h_kernel<<<512, 256, 0, s1>>>(wo, w + OFF_WO);
    cudaEventRecord(e1, s1);

    // main stream
    pack_bias<<<8, 256>>>(bq, bk, bv, bias);
    pack_qkv<<<2048, 256>>>(wq, wk, wv, w + OFF_QKV);
    rmsnorm_kernel<<<M, 256>>>(x, ln1, hh);

    gemm_h<<<dim3(16, 64), thr, GSMEM>>>(hh, w + OFF_QKV, nullptr, qkv,
                                         M, 2048, 1024, bias, nullptr, 0, 0, nullptr);

    rope_table<<<256, 256>>>(ct, st);
    rope_apply<<<24576, 256>>>(qkv, ct, st);

    flash16<<<dim3(32, 16, 4), 256, FLASH_SMEM>>>(qkv, aoh);

    // join side stream before first consumer of packed WO/GU/DN
    cudaStreamWaitEvent(0, e1, 0);

    // out = x + attn @ Wo
    gemm_h<<<dim3(8, 64), thr, GSMEM>>>(aoh, w + OFF_WO, out, nullptr,
                                        M, 1024, 1024, nullptr, x, 0, 0, nullptr);

    rmsnorm_kernel<<<M, 256>>>(out, ln2, hh);

    // fused gate|up (+experts) GEMM with swiglu epilogue -> act[T, 8192]
    gemm_h<<<dim3(128, 64), thr, GSMEM>>>(hh, w + OFF_GU, nullptr, act,
                                          M, 16384, 1024, nullptr, nullptr, 0, 1, emask);

    // fused down: out += act @ [Wd ; Ed]
    gemm_h<<<dim3(8, 64), thr, GSMEM>>>(act, w + OFF_DN, out, nullptr,
                                        M, 1024, 8192, nullptr, nullptr, 1, 0, nullptr);
}

// round 16
// speedup vs baseline: 1.0727x; 1.0213x over previous
#include <cuda_runtime.h>
#include <cuda_fp16.h>
#include <mma.h>
#include <cstdint>

using namespace nvcuda;

// Shapes: B=4, P=2048 -> T=8192 tokens, D=1024, H=16, KV=8, HD=64, F=4096, E=16, FE=256
#define T_TOK 8192
#define NPOS  2048

// ---------------- scratch (device globals) ----------------
__device__ __half sc_hh  [8192*1024];          // rmsnorm out (fp16)
__device__ __half sc_qkv [8192*2048];          // q|k|v packed fp16
__device__ __half sc_aoh [8192*1024];          // attention out fp16
__device__ __half sc_act [(size_t)8192*8192];  // swiglu activations fp16
__device__ float  sc_cos [2048*32];
__device__ float  sc_sin [2048*32];
__device__ float  sc_bias[2048];
__device__ __half sc_w   [28311552];           // packed fp16 weights

// packed weight offsets (elements)
#define OFF_QKV 0                 // [1024, 2048]  (q-cols pre-scaled by 1/8)
#define OFF_WO  2097152           // [1024, 1024]
#define OFF_GU  3145728           // [1024, 16384] col-interleaved g/u
#define OFF_DN  19922944          // [8192, 1024]

// ---------------- weight packing ----------------
__global__ __launch_bounds__(256)
void f2h_kernel(const float* __restrict__ s, __half* __restrict__ d)
{
    size_t i = ((size_t)blockIdx.x * 256 + threadIdx.x) * 8;
    float4 a = *(const float4*)(s + i);
    float4 b = *(const float4*)(s + i + 4);
    __half2 h0 = __floats2half2_rn(a.x, a.y);
    __half2 h1 = __floats2half2_rn(a.z, a.w);
    __half2 h2 = __floats2half2_rn(b.x, b.y);
    __half2 h3 = __floats2half2_rn(b.z, b.w);
    uint4 o;
    o.x = *(uint32_t*)&h0; o.y = *(uint32_t*)&h1;
    o.z = *(uint32_t*)&h2; o.w = *(uint32_t*)&h3;
    *(uint4*)(d + i) = o;
}

// 4 elems/thread; q-region (c<1024) folded by 0.125 (attention 1/sqrt(64) scale)
__global__ __launch_bounds__(256)
void pack_qkv(const float* __restrict__ wq, const float* __restrict__ wk,
              const float* __restrict__ wv, __half* __restrict__ d)
{
    int i = (blockIdx.x * 256 + threadIdx.x) * 4;   // 1024*2048 elems
    int r = i >> 11, c = i & 2047;
    float4 v;
    float sc = 1.0f;
    if (c < 1024)      { v = *(const float4*)(wq + (size_t)r * 1024 + c); sc = 0.125f; }
    else if (c < 1536)   v = *(const float4*)(wk + (size_t)r * 512 + (c - 1024));
    else                 v = *(const float4*)(wv + (size_t)r * 512 + (c - 1536));
    __half2 h0 = __floats2half2_rn(v.x * sc, v.y * sc);
    __half2 h1 = __floats2half2_rn(v.z * sc, v.w * sc);
    uint2 o; o.x = *(uint32_t*)&h0; o.y = *(uint32_t*)&h1;
    *(uint2*)(d + i) = o;
}

__global__ __launch_bounds__(256)
void pack_bias(const float* __restrict__ bq, const float* __restrict__ bk,
               const float* __restrict__ bv, float* __restrict__ d)
{
    int c = blockIdx.x * 256 + threadIdx.x;     // 2048
    float v;
    if (c < 1024)      v = bq[c] * 0.125f;
    else if (c < 1536) v = bk[c - 1024];
    else               v = bv[c - 1536];
    d[c] = v;
}

// one (gate,up) pair per thread: stride-1 reads on both sources, 32-bit write
__global__ __launch_bounds__(256)
void pack_gu(const float* __restrict__ wg, const float* __restrict__ wu,
             const float* __restrict__ eg, const float* __restrict__ eu,
             __half* __restrict__ d)
{
    size_t p = (size_t)blockIdx.x * 256 + threadIdx.x;  // 1024*8192 pairs
    int r = (int)(p >> 13), j = (int)(p & 8191);
    float g, u;
    if (j < 4096) {
        g = wg[(size_t)r * 4096 + j];
        u = wu[(size_t)r * 4096 + j];
    } else {
        int jj = j - 4096, e = jj >> 8, f = jj & 255;
        size_t idx = ((size_t)e * 1024 + r) * 256 + f;
        g = eg[idx];
        u = eu[idx];
    }
    __half2 h = __floats2half2_rn(g, u);
    *(uint32_t*)(d + p * 2) = *(uint32_t*)&h;
}

// 8 elems/thread, rows are 1024-contiguous in both sources
__global__ __launch_bounds__(256)
void pack_down(const float* __restrict__ wd, const float* __restrict__ ed,
               __half* __restrict__ d)
{
    size_t i = ((size_t)blockIdx.x * 256 + threadIdx.x) * 8;  // 8192*1024 elems
    int r = (int)(i >> 10), c = (int)(i & 1023);
    const float* src;
    if (r < 4096) src = wd + (size_t)r * 1024 + c;
    else {
        int r2 = r - 4096, e = r2 >> 8, f = r2 & 255;
        src = ed + ((size_t)e * 256 + f) * 1024 + c;
    }
    float4 a = *(const float4*)(src);
    float4 b = *(const float4*)(src + 4);
    __half2 h0 = __floats2half2_rn(a.x, a.y);
    __half2 h1 = __floats2half2_rn(a.z, a.w);
    __half2 h2 = __floats2half2_rn(b.x, b.y);
    __half2 h3 = __floats2half2_rn(b.z, b.w);
    uint4 o;
    o.x = *(uint32_t*)&h0; o.y = *(uint32_t*)&h1;
    o.z = *(uint32_t*)&h2; o.w = *(uint32_t*)&h3;
    *(uint4*)(d + i) = o;
}

// ---------------- rmsnorm (fp32 in -> fp16 out) ----------------
__global__ __launch_bounds__(256)
void rmsnorm_kernel(const float* __restrict__ x, const float* __restrict__ w,
                    __half* __restrict__ out)
{
    int t = blockIdx.x;
    const float* xr = x + (size_t)t * 1024;
    __half* orow = out + (size_t)t * 1024;
    int tid = threadIdx.x;

    float4 v = *(const float4*)(xr + tid * 4);
    float s = v.x*v.x + v.y*v.y + v.z*v.z + v.w*v.w;
    #pragma unroll
    for (int o = 16; o; o >>= 1) s += __shfl_xor_sync(0xffffffffu, s, o);
    __shared__ float ws[8];
    if ((tid & 31) == 0) ws[tid >> 5] = s;
    __syncthreads();
    if (tid < 8) {
        float t2 = ws[tid];
        #pragma unroll
        for (int o = 4; o; o >>= 1) t2 += __shfl_xor_sync(0xffu, t2, o);
        if (tid == 0) ws[0] = t2;
    }
    __syncthreads();
    float rinv = rsqrtf(ws[0] * (1.0f / 1024.0f) + 1e-6f);
    float4 wv = *(const float4*)(w + tid * 4);
    __half2 r0 = __floats2half2_rn(v.x * rinv * wv.x, v.y * rinv * wv.y);
    __half2 r1 = __floats2half2_rn(v.z * rinv * wv.z, v.w * rinv * wv.w);
    uint2 o;
    o.x = *(uint32_t*)&r0; o.y = *(uint32_t*)&r1;
    *(uint2*)(orow + tid * 4) = o;
}

// ---------------- pipelined fp16 GEMM, 4 warps x 64x64, KC=32, 3 stages -----
// (best config: 128 thr/CTA, 3 CTAs/SM, regs<=170)
// grid.z = split-K chunk (kbase = z*K); lda = A row stride (= total K).
// red=1: epilogue does red.global.add.f32 into C (order-independent accumulate).
#define GBK   32
#define GLDA  40
#define GLDB  136
#define ASTG  (128 * GLDA)
#define BSTG  (GBK * GLDB)
#define NSTG  3
#define GSMEM ((NSTG * (ASTG + BSTG)) * 2)   // 56832 B -> 3 CTAs/SM

__device__ __forceinline__ void cp16(uint32_t saddr, const void* g)
{
    asm volatile("cp.async.cg.shared.global [%0], [%1], 16;\n" :: "r"(saddr), "l"(g));
}
#define CP_COMMIT() asm volatile("cp.async.commit_group;\n" ::)
#define CP_WAIT1()  asm volatile("cp.async.wait_group 1;\n" ::)
#define CP_WAIT0()  asm volatile("cp.async.wait_group 0;\n" ::)

__global__ __launch_bounds__(128, 3)
void gemm_h(const __half* __restrict__ A, const __half* __restrict__ B,
            float* __restrict__ C, __half* __restrict__ Ch,
            int M, int N, int K, int lda,
            const float* __restrict__ bias, const float* __restrict__ res,
            int red, int swiglu, const float* __restrict__ mask)
{
    extern __shared__ __half sm[];
    __half* As = sm;
    __half* Bs = sm + NSTG * ASTG;
    uint32_t smemBase = (uint32_t)__cvta_generic_to_shared(sm);

    int bm = blockIdx.y * 128, bn = blockIdx.x * 128;
    int kbase = blockIdx.z * K;
    int tid = threadIdx.x, wid = tid >> 5, lane = tid & 31;
    int wm = (wid >> 1) * 64, wn = (wid & 1) * 64;

    wmma::fragment<wmma::accumulator, 16, 16, 16, float> acc[4][4];
    #pragma unroll
    for (int i = 0; i < 4; i++)
        #pragma unroll
        for (int j = 0; j < 4; j++) wmma::fill_fragment(acc[i][j], 0.0f);

    int nk = K / GBK;

    auto prefetch = [&](int s, int k0) {
        uint32_t as = smemBase + (uint32_t)(s * ASTG) * 2;
        uint32_t bs = smemBase + (uint32_t)(NSTG * ASTG + s * BSTG) * 2;
        #pragma unroll
        for (int it = 0; it < 4; it++) {
            int j = tid + it * 128;
            int r = j >> 2, c8 = j & 3;
            cp16(as + (uint32_t)(r * GLDA + c8 * 8) * 2,
                 A + (size_t)(bm + r) * lda + kbase + k0 + c8 * 8);
        }
        #pragma unroll
        for (int it = 0; it < 4; it++) {
            int j = tid + it * 128;
            int r = j >> 4, c8 = j & 15;
            cp16(bs + (uint32_t)(r * GLDB + c8 * 8) * 2,
                 B + (size_t)(kbase + k0 + r) * N + bn + c8 * 8);
        }
    };

    prefetch(0, 0);     CP_COMMIT();
    prefetch(1, GBK);   CP_COMMIT();

    for (int i = 0; i < nk; i++) {
        CP_WAIT1();
        __syncthreads();

        int s = i % NSTG;
        const __half* as = As + s * ASTG;
        const __half* bs = Bs + s * BSTG;
        #pragma unroll 1
        for (int kk = 0; kk < GBK; kk += 16) {
            wmma::fragment<wmma::matrix_a, 16, 16, 16, __half, wmma::row_major> af[4];
            #pragma unroll
            for (int ii = 0; ii < 4; ii++)
                wmma::load_matrix_sync(af[ii], as + (wm + ii * 16) * GLDA + kk, GLDA);
            #pragma unroll
            for (int jj = 0; jj < 4; jj++) {
                wmma::fragment<wmma::matrix_b, 16, 16, 16, __half, wmma::row_major> bf;
                wmma::load_matrix_sync(bf, bs + kk * GLDB + wn + jj * 16, GLDB);
                #pragma unroll
                for (int ii = 0; ii < 4; ii++)
                    wmma::mma_sync(acc[ii][jj], af[ii], bf, acc[ii][jj]);
            }
        }

        int next = i + NSTG - 1;
        if (next < nk) prefetch(next % NSTG, next * GBK);
        CP_COMMIT();
    }

    __syncthreads();

    float* buf = (float*)sm + wid * 256;
    int er = lane >> 1, ec0 = (lane & 1) * 8;
    #pragma unroll 1
    for (int i = 0; i < 4; i++)
        #pragma unroll 1
        for (int j = 0; j < 4; j++) {
            wmma::store_matrix_sync(buf, acc[i][j], 16, wmma::mem_row_major);
            __syncwarp();
            int r0 = bm + wm + i * 16, c0 = bn + wn + j * 16;
            if (swiglu) {
                int tok = r0 + er;
                int jb = (c0 >> 1) + (ec0 >> 1);
                float av[4];
                #pragma unroll
                for (int p = 0; p < 4; p++) {
                    float g = buf[er * 16 + ec0 + 2 * p];
                    float u = buf[er * 16 + ec0 + 2 * p + 1];
                    float a = g / (1.0f + __expf(-g)) * u;
                    int jc = jb + p;
                    if (jc >= 4096) a *= mask[(size_t)tok * 16 + ((jc - 4096) >> 8)];
                    av[p] = a;
                }
                __half2 h01 = __floats2half2_rn(av[0], av[1]);
                __half2 h23 = __floats2half2_rn(av[2], av[3]);
                uint2 o; o.x = *(uint32_t*)&h01; o.y = *(uint32_t*)&h23;
                *(uint2*)(Ch + (size_t)tok * (N >> 1) + jb) = o;
            } else if (red) {
                #pragma unroll
                for (int t2 = 0; t2 < 8; t2++) {
                    int e = lane * 8 + t2;
                    int rr = e >> 4, cc = e & 15;
                    size_t ci = (size_t)(r0 + rr) * N + (c0 + cc);
                    asm volatile("red.global.add.f32 [%0], %1;"
                                 :: "l"(C + ci), "f"(buf[e]) : "memory");
                }
            } else {
                #pragma unroll
                for (int t2 = 0; t2 < 8; t2++) {
                    int e = lane * 8 + t2;
                    int rr = e >> 4, cc = e & 15;
                    float vv = buf[e];
                    if (bias) vv += bias[c0 + cc];
                    size_t ci = (size_t)(r0 + rr) * N + (c0 + cc);
                    if (res)   vv += res[ci];
                    if (Ch) Ch[ci] = __float2half(vv);
                    else    C[ci]  = vv;
                }
            }
            __syncwarp();
        }
}

// ---------------- RoPE ----------------
__global__ void rope_table(float* __restrict__ ct, float* __restrict__ st)
{
    int i = blockIdx.x * 256 + threadIdx.x;
    int p = i >> 5, j = i & 31;
    float inv = powf(10000.0f, -(float)j * (1.0f / 32.0f));
    float ang = (float)p * inv;
    float s, c;
    sincosf(ang, &s, &c);
    ct[i] = c; st[i] = s;
}

__global__ void rope_apply(__half* __restrict__ qkv,
                           const float* __restrict__ ct, const float* __restrict__ st)
{
    int i = blockIdx.x * 256 + threadIdx.x;      // T*24*32 total
    int j = i & 31;
    int hh = (i >> 5) % 24;
    int t = i / (24 * 32);
    int p = t & (NPOS - 1);
    int coff = (hh < 16) ? (hh * 64) : (1024 + (hh - 16) * 64);
    float c = ct[p * 32 + j], s = st[p * 32 + j];
    size_t base = (size_t)t * 2048 + coff;
    float v1 = __half2float(qkv[base + j]);
    float v2 = __half2float(qkv[base + 32 + j]);
    qkv[base + j]      = __float2half(v1 * c - v2 * s);
    qkv[base + 32 + j] = __float2half(v2 * c + v1 * s);
}

// ---------------- fp16 flash attention (causal, GQA 2:1, HD=64, 64-row) ------
// Q pre-scaled by 1/8 (folded into Wq/bq). Heaviest qt launched first.
#define FLD 72
#define FT  4608
#define FLASH_SMEM ((6 * FT) * 2 + (2 * FT + 192) * 4)
__global__ __launch_bounds__(256)
void flash16(const __half* __restrict__ qkv, __half* __restrict__ o)
{
    extern __shared__ __half smh[];
    __half* Qs = smh;
    __half* Ks = Qs + FT;
    __half* Vs = Ks + 2 * FT;
    __half* Ps = Vs + 2 * FT;
    float*  Ss = (float*)(Ps + FT);
    float*  Os = Ss + FT;
    float*  mrow = Os + FT;
    float*  lrow = mrow + 64;
    float*  crow = lrow + 64;
    uint32_t smemBase = (uint32_t)__cvta_generic_to_shared(smh);

    int qt = gridDim.x - 1 - blockIdx.x;   // heaviest blocks first
    int h = blockIdx.y, b = blockIdx.z;
    int tid = threadIdx.x, wid = tid >> 5;
    int kvh = h >> 1;

    const __half* qb = qkv + ((size_t)(b * NPOS + qt * 64)) * 2048 + h * 64;
    for (int it = 0; it < 2; it++) {
        int j = tid + it * 256;
        int r = j >> 3, c8 = j & 7;
        *(uint4*)(Qs + r * FLD + c8 * 8) = *(const uint4*)(qb + (size_t)r * 2048 + c8 * 8);
    }
    for (int i = tid; i < 4096; i += 256) {
        int r = i >> 6, c = i & 63;
        Os[r * FLD + c] = 0.0f;
    }
    if (tid < 64) { mrow[tid] = -1e30f; lrow[tid] = 0.0f; }

    auto pf = [&](int kt, int bi) {
        const __half* kb = qkv + ((size_t)(b * NPOS + kt * 64)) * 2048 + 1024 + kvh * 64;
        uint32_t ks = smemBase + (uint32_t)(FT + bi * FT) * 2;
        uint32_t vs = smemBase + (uint32_t)(3 * FT + bi * FT) * 2;
        #pragma unroll
        for (int it = 0; it < 2; it++) {
            int j = tid + it * 256;
            int r = j >> 3, c8 = j & 7;
            cp16(ks + (uint32_t)(r * FLD + c8 * 8) * 2, kb + (size_t)r * 2048 + c8 * 8);
            cp16(vs + (uint32_t)(r * FLD + c8 * 8) * 2, kb + (size_t)r * 2048 + 512 + c8 * 8);
        }
    };

    pf(0, 0);
    CP_COMMIT();
    __syncthreads();

    int wm = (wid >> 1) * 16, wn = (wid & 1) * 32;

    for (int kt = 0; kt <= qt; kt++) {
        int bi = kt & 1;
        CP_WAIT0();
        __syncthreads();
        if (kt < qt) pf(kt + 1, bi ^ 1);
        CP_COMMIT();

        const __half* kcur = Ks + bi * FT;
        const __half* vcur = Vs + bi * FT;

        {
            wmma::fragment<wmma::accumulator, 16, 16, 16, float> sa[2];
            wmma::fill_fragment(sa[0], 0.0f);
            wmma::fill_fragment(sa[1], 0.0f);
            #pragma unroll
            for (int d = 0; d < 64; d += 16) {
                wmma::fragment<wmma::matrix_a, 16, 16, 16, __half, wmma::row_major> af;
                wmma::load_matrix_sync(af, Qs + wm * FLD + d, FLD);
                #pragma unroll
                for (int jj = 0; jj < 2; jj++) {
                    wmma::fragment<wmma::matrix_b, 16, 16, 16, __half, wmma::col_major> bf;
                    wmma::load_matrix_sync(bf, kcur + (wn + jj * 16) * FLD + d, FLD);
                    wmma::mma_sync(sa[jj], af, bf, sa[jj]);
                }
            }
            wmma::store_matrix_sync(Ss + wm * FLD + wn,      sa[0], FLD, wmma::mem_row_major);
            wmma::store_matrix_sync(Ss + wm * FLD + wn + 16, sa[1], FLD, wmma::mem_row_major);
        }
        __syncthreads();

        {
            int r = tid >> 2, pp = tid & 3;
            int qg = qt * 64 + r;
            float vals[16]; float mx = -1e30f;
            #pragma unroll
            for (int c = 0; c < 16; c++) {
                int col = pp * 16 + c;
                float sv = Ss[r * FLD + col];
                if (kt * 64 + col > qg) sv = -1e30f;
                vals[c] = sv; mx = fmaxf(mx, sv);
            }
            mx = fmaxf(mx, __shfl_xor_sync(0xffffffffu, mx, 1));
            mx = fmaxf(mx, __shfl_xor_sync(0xffffffffu, mx, 2));
            float mold = mrow[r];
            float mnew = fmaxf(mold, mx);
            float sum = 0.0f;
            #pragma unroll
            for (int c = 0; c < 16; c++) {
                float e = __expf(vals[c] - mnew);
                Ps[r * FLD + pp * 16 + c] = __float2half(e);
                sum += e;
            }
            sum += __shfl_xor_sync(0xffffffffu, sum, 1);
            sum += __shfl_xor_sync(0xffffffffu, sum, 2);
            if (pp == 0) {
                float cc = __expf(mold - mnew);
                lrow[r] = lrow[r] * cc + sum;
                mrow[r] = mnew;
                crow[r] = cc;
            }
        }
        __syncthreads();

        {
            wmma::fragment<wmma::accumulator, 16, 16, 16, float> pv[2];
            wmma::fill_fragment(pv[0], 0.0f);
            wmma::fill_fragment(pv[1], 0.0f);
            #pragma unroll
            for (int kk = 0; kk < 64; kk += 16) {
                wmma::fragment<wmma::matrix_a, 16, 16, 16, __half, wmma::row_major> af;
                wmma::load_matrix_sync(af, Ps + wm * FLD + kk, FLD);
                #pragma unroll
                for (int jj = 0; jj < 2; jj++) {
                    wmma::fragment<wmma::matrix_b, 16, 16, 16, __half, wmma::row_major> bf;
                    wmma::load_matrix_sync(bf, vcur + kk * FLD + wn + jj * 16, FLD);
                    wmma::mma_sync(pv[jj], af, bf, pv[jj]);
                }
            }
            wmma::store_matrix_sync(Ss + wm * FLD + wn,      pv[0], FLD, wmma::mem_row_major);
            wmma::store_matrix_sync(Ss + wm * FLD + wn + 16, pv[1], FLD, wmma::mem_row_major);
        }
        __syncthreads();

        for (int i = tid; i < 4096; i += 256) {
            int r = i >> 6, c = i & 63;
            Os[r * FLD + c] = Os[r * FLD + c] * crow[r] + Ss[r * FLD + c];
        }
        __syncthreads();
    }

    __half* ob = o + ((size_t)(b * NPOS + qt * 64)) * 1024 + h * 64;
    for (int i = tid; i < 4096; i += 256) {
        int r = i >> 6, c = i & 63;
        ob[(size_t)r * 1024 + c] = __float2half(Os[r * FLD + c] / lrow[r]);
    }
}

// ---------------- launch ----------------
extern "C" void kernel_launch(void* const* d_in, const int* in_sizes, int n_in,
                              void* d_out, int out_size)
{
    const float* x       = (const float*)d_in[0];
    const float* emask   = (const float*)d_in[1];
    const float* ln1     = (const float*)d_in[2];
    const float* wq      = (const float*)d_in[3];
    const float* bq      = (const float*)d_in[4];
    const float* wk      = (const float*)d_in[5];
    const float* bk      = (const float*)d_in[6];
    const float* wv      = (const float*)d_in[7];
    const float* bv      = (const float*)d_in[8];
    const float* wo      = (const float*)d_in[9];
    const float* ln2     = (const float*)d_in[10];
    const float* w_gate  = (const float*)d_in[11];
    const float* w_up    = (const float*)d_in[12];
    const float* w_down  = (const float*)d_in[13];
    const float* we_gate = (const float*)d_in[14];
    const float* we_up   = (const float*)d_in[15];
    const float* we_down = (const float*)d_in[16];
    float* out = (float*)d_out;

    __half *hh, *qkv, *aoh, *act, *w;
    float *ct, *st, *bias;
    cudaGetSymbolAddress((void**)&hh,   sc_hh);
    cudaGetSymbolAddress((void**)&qkv,  sc_qkv);
    cudaGetSymbolAddress((void**)&aoh,  sc_aoh);
    cudaGetSymbolAddress((void**)&act,  sc_act);
    cudaGetSymbolAddress((void**)&w,    sc_w);
    cudaGetSymbolAddress((void**)&ct,   sc_cos);
    cudaGetSymbolAddress((void**)&st,   sc_sin);
    cudaGetSymbolAddress((void**)&bias, sc_bias);

    cudaFuncSetAttribute(flash16, cudaFuncAttributeMaxDynamicSharedMemorySize, FLASH_SMEM);
    cudaFuncSetAttribute(gemm_h, cudaFuncAttributeMaxDynamicSharedMemorySize, GSMEM);

    const int M = T_TOK;
    dim3 thr(128);

    // fork: big weight packs on a side stream, hidden under qkv/rope/flash
    cudaStream_t s1;
    cudaStreamCreate(&s1);
    cudaEvent_t e0, e1;
    cudaEventCreateWithFlags(&e0, cudaEventDisableTiming);
    cudaEventCreateWithFlags(&e1, cudaEventDisableTiming);
    cudaEventRecord(e0, 0);
    cudaStreamWaitEvent(s1, e0, 0);
    pack_gu<<<32768, 256, 0, s1>>>(w_gate, w_up, we_gate, we_up, w + OFF_GU);
    pack_down<<<4096, 256, 0, s1>>>(w_down, we_down, w + OFF_DN);
    f2h_kernel<<<512, 256, 0, s1>>>(wo, w + OFF_WO);
    cudaEventRecord(e1, s1);

    // main stream
    pack_bias<<<8, 256>>>(bq, bk, bv, bias);
    pack_qkv<<<2048, 256>>>(wq, wk, wv, w + OFF_QKV);
    rmsnorm_kernel<<<M, 256>>>(x, ln1, hh);

    gemm_h<<<dim3(16, 64), thr, GSMEM>>>(hh, w + OFF_QKV, nullptr, qkv,
                                         M, 2048, 1024, 1024, bias, nullptr, 0, 0, nullptr);

    rope_table<<<256, 256>>>(ct, st);
    rope_apply<<<24576, 256>>>(qkv, ct, st);

    flash16<<<dim3(32, 16, 4), 256, FLASH_SMEM>>>(qkv, aoh);

    // join side stream before first consumer of packed WO/GU/DN
    cudaStreamWaitEvent(0, e1, 0);

    // out = x + attn @ Wo
    gemm_h<<<dim3(8, 64), thr, GSMEM>>>(aoh, w + OFF_WO, out, nullptr,
                                        M, 1024, 1024, 1024, nullptr, x, 0, 0, nullptr);

    rmsnorm_kernel<<<M, 256>>>(out, ln2, hh);

    // fused gate|up (+experts) GEMM with swiglu epilogue -> act[T, 8192]
    gemm_h<<<dim3(128, 64), thr, GSMEM>>>(hh, w + OFF_GU, nullptr, act,
                                          M, 16384, 1024, 1024, nullptr, nullptr, 0, 1, emask);

    // fused down, split-K=2: out += act @ [Wd ; Ed] via red.global.add
    gemm_h<<<dim3(8, 64, 2), thr, GSMEM>>>(act, w + OFF_DN, out, nullptr,
                                           M, 1024, 4096, 8192, nullptr, nullptr, 1, 0, nullptr);
}